// round 3
// baseline (speedup 1.0000x reference)
#include <cuda_runtime.h>
#include <mma.h>
#include <math.h>
#include <stdint.h>

using namespace nvcuda;

#define BB 2
#define SS 2048
#define EE 2048
#define HH 16
#define DD 128
#define N3 6144            // 3*EE
#define MM (BB*SS)         // 4096
#define KK EE              // 2048

#define LDA 40             // A smem row stride (floats), 160B = 16B-aligned rows
#define LDB 136            // B smem row stride (floats), 544B = 16B-aligned rows

// Scratch (static device globals — allowed; no runtime allocation)
__device__ float g_qkv[(size_t)MM * N3];          // raw qkv, [b*S+s][3*E]
__device__ float g_qT[(size_t)BB * HH * DD * SS]; // Q roped+scaled, [b][h][d][s]
__device__ float g_kT[(size_t)BB * HH * DD * SS]; // K roped,        [b][h][d][s]

// ---------------------------------------------------------------------------
// cp.async helpers
// ---------------------------------------------------------------------------
__device__ __forceinline__ void cp_async16(void* dst_smem, const void* src_gmem) {
    unsigned int dst = (unsigned int)__cvta_generic_to_shared(dst_smem);
    asm volatile("cp.async.cg.shared.global [%0], [%1], 16;\n" :: "r"(dst), "l"(src_gmem));
}
__device__ __forceinline__ void cp_commit() {
    asm volatile("cp.async.commit_group;\n" ::: "memory");
}
template <int N>
__device__ __forceinline__ void cp_wait() {
    asm volatile("cp.async.wait_group %0;\n" :: "n"(N) : "memory");
}

// ---------------------------------------------------------------------------
// Kernel 1: QKV GEMM (M=4096, N=6144, K=2048) via tf32 wmma (tensor cores).
// 128x128 block tile, BK=32, 256 threads (8 warps, 4x2), warp tile 32x64.
// Double-buffered cp.async. Bias added in smem-staged epilogue.
// Dynamic smem: 2*(128*40 + 32*136)*4 = 75776 B (epilogue reuses it as Cs).
// ---------------------------------------------------------------------------
__device__ __forceinline__ void load_tiles(const float* __restrict__ X,
                                           const float* __restrict__ W,
                                           float* As, float* Bs,
                                           int m0, int n0, int kt, int tid) {
    #pragma unroll
    for (int i = 0; i < 4; i++) {               // A: 128 rows x 32 cols
        int idx = tid + i * 256;                 // 1024 float4
        int row = idx >> 3;
        int c4 = (idx & 7) << 2;
        cp_async16(As + row * LDA + c4, X + (size_t)(m0 + row) * KK + kt + c4);
    }
    #pragma unroll
    for (int i = 0; i < 4; i++) {               // B: 32 rows x 128 cols
        int idx = tid + i * 256;
        int row = idx >> 5;
        int c4 = (idx & 31) << 2;
        cp_async16(Bs + row * LDB + c4, W + (size_t)(kt + row) * N3 + n0 + c4);
    }
}

__global__ __launch_bounds__(256) void qkv_gemm(const float* __restrict__ X,
                                                const float* __restrict__ W,
                                                const float* __restrict__ bias) {
    extern __shared__ float sm[];
    float* As[2] = { sm, sm + 128 * LDA };
    float* Bs[2] = { sm + 2 * 128 * LDA, sm + 2 * 128 * LDA + 32 * LDB };

    const int tid = threadIdx.x;
    const int wid = tid >> 5;
    const int wm = wid >> 1;        // 0..3  -> m offset wm*32
    const int wn = wid & 1;         // 0..1  -> n offset wn*64
    const int m0 = blockIdx.y * 128;
    const int n0 = blockIdx.x * 128;

    wmma::fragment<wmma::accumulator, 16, 16, 8, float> acc[2][4];
    #pragma unroll
    for (int i = 0; i < 2; i++)
        #pragma unroll
        for (int j = 0; j < 4; j++) wmma::fill_fragment(acc[i][j], 0.0f);

    load_tiles(X, W, As[0], Bs[0], m0, n0, 0, tid);
    cp_commit();

    const int NT = KK / 32;         // 64 k-tiles
    for (int t = 0; t < NT; t++) {
        const int buf = t & 1;
        if (t + 1 < NT) {
            load_tiles(X, W, As[buf ^ 1], Bs[buf ^ 1], m0, n0, (t + 1) * 32, tid);
            cp_commit();
            cp_wait<1>();
        } else {
            cp_wait<0>();
        }
        __syncthreads();

        const float* Asb = As[buf];
        const float* Bsb = Bs[buf];
        #pragma unroll
        for (int kk = 0; kk < 32; kk += 8) {
            wmma::fragment<wmma::matrix_a, 16, 16, 8, wmma::precision::tf32, wmma::row_major> a[2];
            wmma::fragment<wmma::matrix_b, 16, 16, 8, wmma::precision::tf32, wmma::row_major> b[4];
            #pragma unroll
            for (int i = 0; i < 2; i++) {
                wmma::load_matrix_sync(a[i], Asb + (wm * 32 + i * 16) * LDA + kk, LDA);
                #pragma unroll
                for (int e = 0; e < a[i].num_elements; e++)
                    a[i].x[e] = wmma::__float_to_tf32(a[i].x[e]);
            }
            #pragma unroll
            for (int j = 0; j < 4; j++) {
                wmma::load_matrix_sync(b[j], Bsb + kk * LDB + wn * 64 + j * 16, LDB);
                #pragma unroll
                for (int e = 0; e < b[j].num_elements; e++)
                    b[j].x[e] = wmma::__float_to_tf32(b[j].x[e]);
            }
            #pragma unroll
            for (int i = 0; i < 2; i++)
                #pragma unroll
                for (int j = 0; j < 4; j++)
                    wmma::mma_sync(acc[i][j], a[i], b[j], acc[i][j]);
        }
        __syncthreads();
    }

    // Epilogue: stage C in smem (reuse), add bias, vectorized global store.
    float* Cs = sm;                 // 128*128 floats = 64 KB < 75776 B
    #pragma unroll
    for (int i = 0; i < 2; i++)
        #pragma unroll
        for (int j = 0; j < 4; j++)
            wmma::store_matrix_sync(Cs + (size_t)(wm * 32 + i * 16) * 128 + wn * 64 + j * 16,
                                    acc[i][j], 128, wmma::mem_row_major);
    __syncthreads();

    #pragma unroll
    for (int i = 0; i < 16; i++) {
        int idx = tid + i * 256;    // 4096 float4
        int row = idx >> 5;
        int c4 = (idx & 31) << 2;
        float4 c = *(const float4*)(Cs + row * 128 + c4);
        c.x += bias[n0 + c4 + 0];
        c.y += bias[n0 + c4 + 1];
        c.z += bias[n0 + c4 + 2];
        c.w += bias[n0 + c4 + 3];
        *(float4*)(g_qkv + (size_t)(m0 + row) * N3 + n0 + c4) = c;
    }
}

// ---------------------------------------------------------------------------
// Kernel 2: RoPE + transpose.  Reads g_qkv, writes g_qT / g_kT in [b][h][d][s].
// ---------------------------------------------------------------------------
__global__ __launch_bounds__(256) void rope_transpose() {
    __shared__ float tile[32][129];
    const int s0 = blockIdx.x * 32;
    const int h = blockIdx.y;
    const int zz = blockIdx.z;      // b*2 + which (0=q, 1=k)
    const int b = zz >> 1;
    const int which = zz & 1;

    const float* src = g_qkv + ((size_t)(b * SS + s0)) * N3 + which * EE + h * DD;
    for (int idx = threadIdx.x; idx < 32 * 128; idx += 256) {
        int sl = idx >> 7, d = idx & 127;
        tile[sl][d] = src[(size_t)sl * N3 + d];
    }
    __syncthreads();

    float* dst = (which == 0 ? g_qT : g_kT) + ((size_t)(b * HH + h) * DD) * SS + s0;
    const float scale = (which == 0) ? 0.08838834764831845f : 1.0f;  // 1/sqrt(128)
    for (int idx = threadIdx.x; idx < 32 * 128; idx += 256) {
        int d = idx >> 5, sl = idx & 31;
        float u = tile[sl][d];
        float w = tile[sl][d ^ 64];
        float rh = (d < 64) ? -w : w;
        float t = (float)((s0 + sl) * 128 + d);
        float sv, cv;
        sincosf(t, &sv, &cv);
        dst[(size_t)d * SS + sl] = (u * cv + rh * sv) * scale;
    }
}

// ---------------------------------------------------------------------------
// Kernel 3: flash attention, fp32 SIMT (unchanged, proven).
// ---------------------------------------------------------------------------
__global__ __launch_bounds__(256, 1) void attn_kernel(float* __restrict__ out) {
    extern __shared__ float smx[];
    float* Qt = smx;                   // 16384 floats
    float* Kt = Qt + 128 * 128;        //  8192 floats
    float* Vs = Kt + 64 * 128;         // 16384 floats
    float* Ps = Vs + 128 * 128;        // 16384 floats

    const int tid = threadIdx.x;
    const int tx = tid & 15;
    const int ty = tid >> 4;
    const int s0 = blockIdx.x * 128;
    const int h = blockIdx.y;
    const int b = blockIdx.z;

    const float* qbase = g_qT + (size_t)(b * HH + h) * DD * SS;
    const float* kbase = g_kT + (size_t)(b * HH + h) * DD * SS;
    const float* vbase = g_qkv + (size_t)b * SS * N3 + 2 * EE + h * DD;

    #pragma unroll
    for (int i = 0; i < 16; i++) {
        int lin = tid + i * 256;
        int d = lin >> 5;
        int m = (lin & 31) << 2;
        float4 v = *(const float4*)(qbase + (size_t)d * SS + s0 + m);
        *(float4*)(&Qt[d * 128 + m]) = v;
    }

    float O[8][8];
    #pragma unroll
    for (int i = 0; i < 8; i++)
        #pragma unroll
        for (int j = 0; j < 8; j++) O[i][j] = 0.0f;
    float mrow[8], lrow[8];
    #pragma unroll
    for (int i = 0; i < 8; i++) { mrow[i] = -1e30f; lrow[i] = 0.0f; }

    for (int kt = 0; kt < SS / 128; kt++) {
        const int n0 = kt * 128;
        __syncthreads();

        #pragma unroll
        for (int i = 0; i < 16; i++) {
            int lin = tid + i * 256;
            int n = lin >> 5;
            int dv = (lin & 31) << 2;
            float4 v = *(const float4*)(vbase + (size_t)(n0 + n) * N3 + dv);
            *(float4*)(&Vs[n * 128 + dv]) = v;
        }
        #pragma unroll
        for (int i = 0; i < 8; i++) {
            int lin = tid + i * 256;
            int d = lin >> 5;
            int m = (lin & 31) << 2;
            float4 v = *(const float4*)(kbase + (size_t)d * SS + n0 + m);
            *(float4*)(&Kt[d * 128 + m]) = v;
        }
        __syncthreads();

        float sacc[8][8];
        #pragma unroll
        for (int i = 0; i < 8; i++)
            #pragma unroll
            for (int j = 0; j < 8; j++) sacc[i][j] = 0.0f;

        #pragma unroll 4
        for (int d = 0; d < 64; d++) {
            float4 a0 = *(const float4*)(&Qt[d * 128 + ty * 8]);
            float4 a1 = *(const float4*)(&Qt[d * 128 + ty * 8 + 4]);
            float4 b0 = *(const float4*)(&Kt[d * 128 + tx * 8]);
            float4 b1 = *(const float4*)(&Kt[d * 128 + tx * 8 + 4]);
            float av[8] = {a0.x, a0.y, a0.z, a0.w, a1.x, a1.y, a1.z, a1.w};
            float bv[8] = {b0.x, b0.y, b0.z, b0.w, b1.x, b1.y, b1.z, b1.w};
            #pragma unroll
            for (int i = 0; i < 8; i++)
                #pragma unroll
                for (int j = 0; j < 8; j++) sacc[i][j] += av[i] * bv[j];
        }
        __syncthreads();
        #pragma unroll
        for (int i = 0; i < 8; i++) {
            int lin = tid + i * 256;
            int d = lin >> 5;
            int m = (lin & 31) << 2;
            float4 v = *(const float4*)(kbase + (size_t)(64 + d) * SS + n0 + m);
            *(float4*)(&Kt[d * 128 + m]) = v;
        }
        __syncthreads();
        #pragma unroll 4
        for (int d = 0; d < 64; d++) {
            float4 a0 = *(const float4*)(&Qt[(64 + d) * 128 + ty * 8]);
            float4 a1 = *(const float4*)(&Qt[(64 + d) * 128 + ty * 8 + 4]);
            float4 b0 = *(const float4*)(&Kt[d * 128 + tx * 8]);
            float4 b1 = *(const float4*)(&Kt[d * 128 + tx * 8 + 4]);
            float av[8] = {a0.x, a0.y, a0.z, a0.w, a1.x, a1.y, a1.z, a1.w};
            float bv[8] = {b0.x, b0.y, b0.z, b0.w, b1.x, b1.y, b1.z, b1.w};
            #pragma unroll
            for (int i = 0; i < 8; i++)
                #pragma unroll
                for (int j = 0; j < 8; j++) sacc[i][j] += av[i] * bv[j];
        }

        #pragma unroll
        for (int i = 0; i < 8; i++) {
            float mx = sacc[i][0];
            #pragma unroll
            for (int j = 1; j < 8; j++) mx = fmaxf(mx, sacc[i][j]);
            #pragma unroll
            for (int off = 8; off > 0; off >>= 1)
                mx = fmaxf(mx, __shfl_xor_sync(0xffffffffu, mx, off));
            float mnew = fmaxf(mrow[i], mx);
            float alpha = __expf(mrow[i] - mnew);
            float p[8];
            float ps = 0.0f;
            #pragma unroll
            for (int j = 0; j < 8; j++) {
                p[j] = __expf(sacc[i][j] - mnew);
                ps += p[j];
            }
            float4 p0 = {p[0], p[1], p[2], p[3]};
            float4 p1 = {p[4], p[5], p[6], p[7]};
            *(float4*)(&Ps[(ty * 8 + i) * 128 + tx * 8]) = p0;
            *(float4*)(&Ps[(ty * 8 + i) * 128 + tx * 8 + 4]) = p1;
            #pragma unroll
            for (int off = 8; off > 0; off >>= 1)
                ps += __shfl_xor_sync(0xffffffffu, ps, off);
            lrow[i] = lrow[i] * alpha + ps;
            mrow[i] = mnew;
            #pragma unroll
            for (int j = 0; j < 8; j++) O[i][j] *= alpha;
        }
        __syncthreads();

        #pragma unroll 2
        for (int k = 0; k < 128; k++) {
            float4 v0 = *(const float4*)(&Vs[k * 128 + tx * 8]);
            float4 v1 = *(const float4*)(&Vs[k * 128 + tx * 8 + 4]);
            float vv[8] = {v0.x, v0.y, v0.z, v0.w, v1.x, v1.y, v1.z, v1.w};
            #pragma unroll
            for (int i = 0; i < 8; i++) {
                float p = Ps[(ty * 8 + i) * 128 + k];
                #pragma unroll
                for (int j = 0; j < 8; j++) O[i][j] += p * vv[j];
            }
        }
    }

    #pragma unroll
    for (int i = 0; i < 8; i++) {
        float inv = 1.0f / lrow[i];
        int s = s0 + ty * 8 + i;
        float* op = out + ((size_t)(b * SS + s) * HH + h) * DD + tx * 8;
        float4 o0, o1;
        o0.x = O[i][0] * inv; o0.y = O[i][1] * inv;
        o0.z = O[i][2] * inv; o0.w = O[i][3] * inv;
        o1.x = O[i][4] * inv; o1.y = O[i][5] * inv;
        o1.z = O[i][6] * inv; o1.w = O[i][7] * inv;
        *(float4*)(op) = o0;
        *(float4*)(op + 4) = o1;
    }
}

// ---------------------------------------------------------------------------
extern "C" void kernel_launch(void* const* d_in, const int* in_sizes, int n_in,
                              void* d_out, int out_size) {
    const float* x    = (const float*)d_in[0];
    const float* W    = (const float*)d_in[1];
    const float* bias = (const float*)d_in[2];
    float* out = (float*)d_out;

    const int gemm_smem = (2 * 128 * LDA + 2 * 32 * LDB) * 4;   // 75776
    cudaFuncSetAttribute(qkv_gemm, cudaFuncAttributeMaxDynamicSharedMemorySize, gemm_smem);
    dim3 g1(N3 / 128, MM / 128);        // 48 x 32
    qkv_gemm<<<g1, 256, gemm_smem>>>(x, W, bias);

    dim3 g2(SS / 32, HH, BB * 2);       // 64 x 16 x 4
    rope_transpose<<<g2, 256>>>();

    const int attn_smem = (128 * 128 + 64 * 128 + 128 * 128 + 128 * 128) * 4; // 229376
    cudaFuncSetAttribute(attn_kernel, cudaFuncAttributeMaxDynamicSharedMemorySize, attn_smem);
    dim3 g3(SS / 128, HH, BB);          // 16 x 16 x 2
    attn_kernel<<<g3, 256, attn_smem>>>(out);
}

// round 5
// speedup vs baseline: 1.5929x; 1.5929x over previous
#include <cuda_runtime.h>
#include <mma.h>
#include <math.h>
#include <stdint.h>

using namespace nvcuda;

#define BB 2
#define SS 2048
#define EE 2048
#define HH 16
#define DD 128
#define N3 6144            // 3*EE
#define MM (BB*SS)         // 4096
#define KK EE              // 2048

#define LDA 40             // A smem row stride (floats)
#define LDB 136            // B smem row stride (floats)

// Scratch (static device globals — allowed; no runtime allocation)
__device__ float g_qkv[(size_t)MM * N3];          // raw qkv, [b*S+s][3*E]
__device__ float g_xr [(size_t)MM * KK];          // X pre-rounded to tf32 (RN)
__device__ float g_wr [(size_t)KK * N3];          // W pre-rounded to tf32 (RN), [k][n]
__device__ float g_qT [(size_t)BB * HH * DD * SS]; // Q roped+scaled, [b][h][d][s]
__device__ float g_kT [(size_t)BB * HH * DD * SS]; // K roped,        [b][h][d][s]

// ---------------------------------------------------------------------------
// Helpers
// ---------------------------------------------------------------------------
__device__ __forceinline__ float tf32_rn(float f) {
    unsigned int u;
    asm("cvt.rn.tf32.f32 %0, %1;" : "=r"(u) : "f"(f));
    return __uint_as_float(u);
}
__device__ __forceinline__ void cp_async16(void* dst_smem, const void* src_gmem) {
    unsigned int dst = (unsigned int)__cvta_generic_to_shared(dst_smem);
    asm volatile("cp.async.cg.shared.global [%0], [%1], 16;\n" :: "r"(dst), "l"(src_gmem));
}
__device__ __forceinline__ void cp_commit() {
    asm volatile("cp.async.commit_group;\n" ::: "memory");
}
template <int N>
__device__ __forceinline__ void cp_wait() {
    asm volatile("cp.async.wait_group %0;\n" :: "n"(N) : "memory");
}

// ---------------------------------------------------------------------------
// Prep kernel A: RN-round X to tf32
// ---------------------------------------------------------------------------
__global__ __launch_bounds__(256) void round_x(const float* __restrict__ X) {
    size_t i = ((size_t)blockIdx.x * 256 + threadIdx.x) * 4;
    float4 v = *(const float4*)(X + i);
    v.x = tf32_rn(v.x); v.y = tf32_rn(v.y); v.z = tf32_rn(v.z); v.w = tf32_rn(v.w);
    *(float4*)(g_xr + i) = v;
}
// Prep kernel B: RN-round W to tf32 (layout unchanged, [k][n])
__global__ __launch_bounds__(256) void round_w(const float* __restrict__ W) {
    size_t i = ((size_t)blockIdx.x * 256 + threadIdx.x) * 4;
    float4 v = *(const float4*)(W + i);
    v.x = tf32_rn(v.x); v.y = tf32_rn(v.y); v.z = tf32_rn(v.z); v.w = tf32_rn(v.w);
    *(float4*)(g_wr + i) = v;
}

// ---------------------------------------------------------------------------
// Kernel 1: QKV GEMM (M=4096, N=6144, K=2048) via tf32 wmma.
// 128x128 block tile, BK=32, 512 threads (16 warps, 4x4), warp tile 32x32.
// Inputs pre-rounded to tf32 -> NO per-element cvt in the hot loop.
// Double-buffered cp.async. Bias added in smem-staged epilogue.
// Dynamic smem: 2*(128*40 + 32*136)*4 = 75776 B (epilogue reuses it as Cs).
// ---------------------------------------------------------------------------
__device__ __forceinline__ void load_tiles(float* As, float* Bs,
                                           int m0, int n0, int kt, int tid) {
    #pragma unroll
    for (int i = 0; i < 2; i++) {               // A: 128 rows x 32 cols = 1024 f4
        int idx = tid + i * 512;
        int row = idx >> 3;
        int c4 = (idx & 7) << 2;
        cp_async16(As + row * LDA + c4, g_xr + (size_t)(m0 + row) * KK + kt + c4);
    }
    #pragma unroll
    for (int i = 0; i < 2; i++) {               // B: 32 rows x 128 cols = 1024 f4
        int idx = tid + i * 512;
        int row = idx >> 5;
        int c4 = (idx & 31) << 2;
        cp_async16(Bs + row * LDB + c4, g_wr + (size_t)(kt + row) * N3 + n0 + c4);
    }
}

__global__ __launch_bounds__(512) void qkv_gemm(const float* __restrict__ bias) {
    extern __shared__ float sm[];
    float* As[2] = { sm, sm + 128 * LDA };
    float* Bs[2] = { sm + 2 * 128 * LDA, sm + 2 * 128 * LDA + 32 * LDB };

    const int tid = threadIdx.x;
    const int wid = tid >> 5;
    const int wm = wid & 3;         // 0..3 -> m offset wm*32
    const int wn = wid >> 2;        // 0..3 -> n offset wn*32
    const int m0 = blockIdx.y * 128;
    const int n0 = blockIdx.x * 128;

    wmma::fragment<wmma::accumulator, 16, 16, 8, float> acc[2][2];
    #pragma unroll
    for (int i = 0; i < 2; i++)
        #pragma unroll
        for (int j = 0; j < 2; j++) wmma::fill_fragment(acc[i][j], 0.0f);

    load_tiles(As[0], Bs[0], m0, n0, 0, tid);
    cp_commit();

    const int NT = KK / 32;         // 64 k-tiles
    for (int t = 0; t < NT; t++) {
        const int buf = t & 1;
        if (t + 1 < NT) {
            load_tiles(As[buf ^ 1], Bs[buf ^ 1], m0, n0, (t + 1) * 32, tid);
            cp_commit();
            cp_wait<1>();
        } else {
            cp_wait<0>();
        }
        __syncthreads();

        const float* Asb = As[buf];
        const float* Bsb = Bs[buf];
        #pragma unroll
        for (int kk = 0; kk < 32; kk += 8) {
            wmma::fragment<wmma::matrix_a, 16, 16, 8, wmma::precision::tf32, wmma::row_major> a[2];
            wmma::fragment<wmma::matrix_b, 16, 16, 8, wmma::precision::tf32, wmma::row_major> b[2];
            #pragma unroll
            for (int i = 0; i < 2; i++)
                wmma::load_matrix_sync(a[i], Asb + (wm * 32 + i * 16) * LDA + kk, LDA);
            #pragma unroll
            for (int j = 0; j < 2; j++)
                wmma::load_matrix_sync(b[j], Bsb + kk * LDB + wn * 32 + j * 16, LDB);
            #pragma unroll
            for (int i = 0; i < 2; i++)
                #pragma unroll
                for (int j = 0; j < 2; j++)
                    wmma::mma_sync(acc[i][j], a[i], b[j], acc[i][j]);
        }
        __syncthreads();
    }

    // Epilogue: stage C in smem (reuse), add bias, vectorized global store.
    float* Cs = sm;                 // 128*128 floats = 64 KB < 75776 B
    #pragma unroll
    for (int i = 0; i < 2; i++)
        #pragma unroll
        for (int j = 0; j < 2; j++)
            wmma::store_matrix_sync(Cs + (size_t)(wm * 32 + i * 16) * 128 + wn * 32 + j * 16,
                                    acc[i][j], 128, wmma::mem_row_major);
    __syncthreads();

    #pragma unroll
    for (int i = 0; i < 8; i++) {
        int idx = tid + i * 512;    // 4096 float4
        int row = idx >> 5;
        int c4 = (idx & 31) << 2;
        float4 c = *(const float4*)(Cs + row * 128 + c4);
        c.x += bias[n0 + c4 + 0];
        c.y += bias[n0 + c4 + 1];
        c.z += bias[n0 + c4 + 2];
        c.w += bias[n0 + c4 + 3];
        *(float4*)(g_qkv + (size_t)(m0 + row) * N3 + n0 + c4) = c;
    }
}

// ---------------------------------------------------------------------------
// Kernel 2: RoPE + transpose.  Reads g_qkv, writes g_qT / g_kT in [b][h][d][s].
// ---------------------------------------------------------------------------
__global__ __launch_bounds__(256) void rope_transpose() {
    __shared__ float tile[32][129];
    const int s0 = blockIdx.x * 32;
    const int h = blockIdx.y;
    const int zz = blockIdx.z;      // b*2 + which (0=q, 1=k)
    const int b = zz >> 1;
    const int which = zz & 1;

    const float* src = g_qkv + ((size_t)(b * SS + s0)) * N3 + which * EE + h * DD;
    for (int idx = threadIdx.x; idx < 32 * 128; idx += 256) {
        int sl = idx >> 7, d = idx & 127;
        tile[sl][d] = src[(size_t)sl * N3 + d];
    }
    __syncthreads();

    float* dst = (which == 0 ? g_qT : g_kT) + ((size_t)(b * HH + h) * DD) * SS + s0;
    const float scale = (which == 0) ? 0.08838834764831845f : 1.0f;  // 1/sqrt(128)
    for (int idx = threadIdx.x; idx < 32 * 128; idx += 256) {
        int d = idx >> 5, sl = idx & 31;
        float u = tile[sl][d];
        float w = tile[sl][d ^ 64];
        float rh = (d < 64) ? -w : w;
        float t = (float)((s0 + sl) * 128 + d);
        float sv, cv;
        sincosf(t, &sv, &cv);
        dst[(size_t)d * SS + sl] = (u * cv + rh * sv) * scale;
    }
}

// ---------------------------------------------------------------------------
// Kernel 3: flash attention, fp32 SIMT (unchanged, proven).
// ---------------------------------------------------------------------------
__global__ __launch_bounds__(256, 1) void attn_kernel(float* __restrict__ out) {
    extern __shared__ float smf[];
    float* Qt = smf;                   // 16384 floats
    float* Kt = Qt + 128 * 128;        //  8192 floats
    float* Vs = Kt + 64 * 128;         // 16384 floats
    float* Ps = Vs + 128 * 128;        // 16384 floats

    const int tid = threadIdx.x;
    const int tx = tid & 15;
    const int ty = tid >> 4;
    const int s0 = blockIdx.x * 128;
    const int h = blockIdx.y;
    const int b = blockIdx.z;

    const float* qbase = g_qT + (size_t)(b * HH + h) * DD * SS;
    const float* kbase = g_kT + (size_t)(b * HH + h) * DD * SS;
    const float* vbase = g_qkv + (size_t)b * SS * N3 + 2 * EE + h * DD;

    #pragma unroll
    for (int i = 0; i < 16; i++) {
        int lin = tid + i * 256;
        int d = lin >> 5;
        int m = (lin & 31) << 2;
        float4 v = *(const float4*)(qbase + (size_t)d * SS + s0 + m);
        *(float4*)(&Qt[d * 128 + m]) = v;
    }

    float O[8][8];
    #pragma unroll
    for (int i = 0; i < 8; i++)
        #pragma unroll
        for (int j = 0; j < 8; j++) O[i][j] = 0.0f;
    float mrow[8], lrow[8];
    #pragma unroll
    for (int i = 0; i < 8; i++) { mrow[i] = -1e30f; lrow[i] = 0.0f; }

    for (int kt = 0; kt < SS / 128; kt++) {
        const int n0 = kt * 128;
        __syncthreads();

        #pragma unroll
        for (int i = 0; i < 16; i++) {
            int lin = tid + i * 256;
            int n = lin >> 5;
            int dv = (lin & 31) << 2;
            float4 v = *(const float4*)(vbase + (size_t)(n0 + n) * N3 + dv);
            *(float4*)(&Vs[n * 128 + dv]) = v;
        }
        #pragma unroll
        for (int i = 0; i < 8; i++) {
            int lin = tid + i * 256;
            int d = lin >> 5;
            int m = (lin & 31) << 2;
            float4 v = *(const float4*)(kbase + (size_t)d * SS + n0 + m);
            *(float4*)(&Kt[d * 128 + m]) = v;
        }
        __syncthreads();

        float sacc[8][8];
        #pragma unroll
        for (int i = 0; i < 8; i++)
            #pragma unroll
            for (int j = 0; j < 8; j++) sacc[i][j] = 0.0f;

        #pragma unroll 4
        for (int d = 0; d < 64; d++) {
            float4 a0 = *(const float4*)(&Qt[d * 128 + ty * 8]);
            float4 a1 = *(const float4*)(&Qt[d * 128 + ty * 8 + 4]);
            float4 b0 = *(const float4*)(&Kt[d * 128 + tx * 8]);
            float4 b1 = *(const float4*)(&Kt[d * 128 + tx * 8 + 4]);
            float av[8] = {a0.x, a0.y, a0.z, a0.w, a1.x, a1.y, a1.z, a1.w};
            float bv[8] = {b0.x, b0.y, b0.z, b0.w, b1.x, b1.y, b1.z, b1.w};
            #pragma unroll
            for (int i = 0; i < 8; i++)
                #pragma unroll
                for (int j = 0; j < 8; j++) sacc[i][j] += av[i] * bv[j];
        }
        __syncthreads();
        #pragma unroll
        for (int i = 0; i < 8; i++) {
            int lin = tid + i * 256;
            int d = lin >> 5;
            int m = (lin & 31) << 2;
            float4 v = *(const float4*)(kbase + (size_t)(64 + d) * SS + n0 + m);
            *(float4*)(&Kt[d * 128 + m]) = v;
        }
        __syncthreads();
        #pragma unroll 4
        for (int d = 0; d < 64; d++) {
            float4 a0 = *(const float4*)(&Qt[(64 + d) * 128 + ty * 8]);
            float4 a1 = *(const float4*)(&Qt[(64 + d) * 128 + ty * 8 + 4]);
            float4 b0 = *(const float4*)(&Kt[d * 128 + tx * 8]);
            float4 b1 = *(const float4*)(&Kt[d * 128 + tx * 8 + 4]);
            float av[8] = {a0.x, a0.y, a0.z, a0.w, a1.x, a1.y, a1.z, a1.w};
            float bv[8] = {b0.x, b0.y, b0.z, b0.w, b1.x, b1.y, b1.z, b1.w};
            #pragma unroll
            for (int i = 0; i < 8; i++)
                #pragma unroll
                for (int j = 0; j < 8; j++) sacc[i][j] += av[i] * bv[j];
        }

        #pragma unroll
        for (int i = 0; i < 8; i++) {
            float mx = sacc[i][0];
            #pragma unroll
            for (int j = 1; j < 8; j++) mx = fmaxf(mx, sacc[i][j]);
            #pragma unroll
            for (int off = 8; off > 0; off >>= 1)
                mx = fmaxf(mx, __shfl_xor_sync(0xffffffffu, mx, off));
            float mnew = fmaxf(mrow[i], mx);
            float alpha = __expf(mrow[i] - mnew);
            float p[8];
            float ps = 0.0f;
            #pragma unroll
            for (int j = 0; j < 8; j++) {
                p[j] = __expf(sacc[i][j] - mnew);
                ps += p[j];
            }
            float4 p0 = {p[0], p[1], p[2], p[3]};
            float4 p1 = {p[4], p[5], p[6], p[7]};
            *(float4*)(&Ps[(ty * 8 + i) * 128 + tx * 8]) = p0;
            *(float4*)(&Ps[(ty * 8 + i) * 128 + tx * 8 + 4]) = p1;
            #pragma unroll
            for (int off = 8; off > 0; off >>= 1)
                ps += __shfl_xor_sync(0xffffffffu, ps, off);
            lrow[i] = lrow[i] * alpha + ps;
            mrow[i] = mnew;
            #pragma unroll
            for (int j = 0; j < 8; j++) O[i][j] *= alpha;
        }
        __syncthreads();

        #pragma unroll 2
        for (int k = 0; k < 128; k++) {
            float4 v0 = *(const float4*)(&Vs[k * 128 + tx * 8]);
            float4 v1 = *(const float4*)(&Vs[k * 128 + tx * 8 + 4]);
            float vv[8] = {v0.x, v0.y, v0.z, v0.w, v1.x, v1.y, v1.z, v1.w};
            #pragma unroll
            for (int i = 0; i < 8; i++) {
                float p = Ps[(ty * 8 + i) * 128 + k];
                #pragma unroll
                for (int j = 0; j < 8; j++) O[i][j] += p * vv[j];
            }
        }
    }

    #pragma unroll
    for (int i = 0; i < 8; i++) {
        float inv = 1.0f / lrow[i];
        int s = s0 + ty * 8 + i;
        float* op = out + ((size_t)(b * SS + s) * HH + h) * DD + tx * 8;
        float4 o0, o1;
        o0.x = O[i][0] * inv; o0.y = O[i][1] * inv;
        o0.z = O[i][2] * inv; o0.w = O[i][3] * inv;
        o1.x = O[i][4] * inv; o1.y = O[i][5] * inv;
        o1.z = O[i][6] * inv; o1.w = O[i][7] * inv;
        *(float4*)(op) = o0;
        *(float4*)(op + 4) = o1;
    }
}

// ---------------------------------------------------------------------------
extern "C" void kernel_launch(void* const* d_in, const int* in_sizes, int n_in,
                              void* d_out, int out_size) {
    const float* x    = (const float*)d_in[0];
    const float* W    = (const float*)d_in[1];
    const float* bias = (const float*)d_in[2];
    float* out = (float*)d_out;

    // Prep: RN-round X and W to tf32 (removes all cvt work from the GEMM loop)
    round_x<<<(int)((size_t)MM * KK / 1024), 256>>>(x);
    round_w<<<(int)((size_t)KK * N3 / 1024), 256>>>(W);

    const int gemm_smem = (2 * 128 * LDA + 2 * 32 * LDB) * 4;   // 75776
    cudaFuncSetAttribute(qkv_gemm, cudaFuncAttributeMaxDynamicSharedMemorySize, gemm_smem);
    dim3 g1(N3 / 128, MM / 128);        // 48 x 32
    qkv_gemm<<<g1, 512, gemm_smem>>>(bias);

    dim3 g2(SS / 32, HH, BB * 2);       // 64 x 16 x 4
    rope_transpose<<<g2, 256>>>();

    const int attn_smem = (128 * 128 + 64 * 128 + 128 * 128 + 128 * 128) * 4; // 229376
    cudaFuncSetAttribute(attn_kernel, cudaFuncAttributeMaxDynamicSharedMemorySize, attn_smem);
    dim3 g3(SS / 128, HH, BB);          // 16 x 16 x 2
    attn_kernel<<<g3, 256, attn_smem>>>(out);
}

// round 6
// speedup vs baseline: 2.5333x; 1.5904x over previous
#include <cuda_runtime.h>
#include <mma.h>
#include <math.h>
#include <stdint.h>

using namespace nvcuda;

#define BB 2
#define SS 2048
#define EE 2048
#define HH 16
#define DD 128
#define N3 6144            // 3*EE
#define MM (BB*SS)         // 4096
#define KK EE              // 2048

#define LDA 40             // GEMM A smem row stride (floats)
#define LDB 136            // GEMM B smem row stride (floats)

// Scratch (static device globals — allowed; no runtime allocation)
__device__ float g_qkv[(size_t)MM * N3];           // raw qkv, [b*S+s][3*E]
__device__ float g_xr [(size_t)MM * KK];           // X pre-rounded to tf32 (RN)
__device__ float g_wr [(size_t)KK * N3];           // W pre-rounded to tf32 (RN)
__device__ float g_q  [(size_t)BB * HH * SS * DD]; // Q roped+scaled, tf32, [b][h][s][d]
__device__ float g_k  [(size_t)BB * HH * SS * DD]; // K roped, tf32, [b][h][s][d]
__device__ float g_v  [(size_t)BB * HH * SS * DD]; // V, tf32, [b][h][s][d]

// ---------------------------------------------------------------------------
// Helpers
// ---------------------------------------------------------------------------
__device__ __forceinline__ float tf32_rn(float f) {
    unsigned int u;
    asm("cvt.rn.tf32.f32 %0, %1;" : "=r"(u) : "f"(f));
    return __uint_as_float(u);
}
__device__ __forceinline__ void cp_async16(void* dst_smem, const void* src_gmem) {
    unsigned int dst = (unsigned int)__cvta_generic_to_shared(dst_smem);
    asm volatile("cp.async.cg.shared.global [%0], [%1], 16;\n" :: "r"(dst), "l"(src_gmem));
}
__device__ __forceinline__ void cp_commit() {
    asm volatile("cp.async.commit_group;\n" ::: "memory");
}
template <int N>
__device__ __forceinline__ void cp_wait() {
    asm volatile("cp.async.wait_group %0;\n" :: "n"(N) : "memory");
}
// mma.sync m16n8k8 tf32, documented lane mapping
__device__ __forceinline__ void mma_tf32(float* c, const unsigned* a, const unsigned* b) {
    asm volatile(
        "mma.sync.aligned.m16n8k8.row.col.f32.tf32.tf32.f32 "
        "{%0,%1,%2,%3}, {%4,%5,%6,%7}, {%8,%9}, {%0,%1,%2,%3};"
        : "+f"(c[0]), "+f"(c[1]), "+f"(c[2]), "+f"(c[3])
        : "r"(a[0]), "r"(a[1]), "r"(a[2]), "r"(a[3]), "r"(b[0]), "r"(b[1]));
}

// ---------------------------------------------------------------------------
// Prep kernels: RN-round X / W to tf32
// ---------------------------------------------------------------------------
__global__ __launch_bounds__(256) void round_x(const float* __restrict__ X) {
    size_t i = ((size_t)blockIdx.x * 256 + threadIdx.x) * 4;
    float4 v = *(const float4*)(X + i);
    v.x = tf32_rn(v.x); v.y = tf32_rn(v.y); v.z = tf32_rn(v.z); v.w = tf32_rn(v.w);
    *(float4*)(g_xr + i) = v;
}
__global__ __launch_bounds__(256) void round_w(const float* __restrict__ W) {
    size_t i = ((size_t)blockIdx.x * 256 + threadIdx.x) * 4;
    float4 v = *(const float4*)(W + i);
    v.x = tf32_rn(v.x); v.y = tf32_rn(v.y); v.z = tf32_rn(v.z); v.w = tf32_rn(v.w);
    *(float4*)(g_wr + i) = v;
}

// ---------------------------------------------------------------------------
// Kernel 1: QKV GEMM (tf32 wmma, 128x128x32, 512 threads) — unchanged from R5
// ---------------------------------------------------------------------------
__device__ __forceinline__ void load_tiles(float* As, float* Bs,
                                           int m0, int n0, int kt, int tid) {
    #pragma unroll
    for (int i = 0; i < 2; i++) {
        int idx = tid + i * 512;
        int row = idx >> 3;
        int c4 = (idx & 7) << 2;
        cp_async16(As + row * LDA + c4, g_xr + (size_t)(m0 + row) * KK + kt + c4);
    }
    #pragma unroll
    for (int i = 0; i < 2; i++) {
        int idx = tid + i * 512;
        int row = idx >> 5;
        int c4 = (idx & 31) << 2;
        cp_async16(Bs + row * LDB + c4, g_wr + (size_t)(kt + row) * N3 + n0 + c4);
    }
}

__global__ __launch_bounds__(512) void qkv_gemm(const float* __restrict__ bias) {
    extern __shared__ float sm[];
    float* As[2] = { sm, sm + 128 * LDA };
    float* Bs[2] = { sm + 2 * 128 * LDA, sm + 2 * 128 * LDA + 32 * LDB };

    const int tid = threadIdx.x;
    const int wid = tid >> 5;
    const int wm = wid & 3;
    const int wn = wid >> 2;
    const int m0 = blockIdx.y * 128;
    const int n0 = blockIdx.x * 128;

    wmma::fragment<wmma::accumulator, 16, 16, 8, float> acc[2][2];
    #pragma unroll
    for (int i = 0; i < 2; i++)
        #pragma unroll
        for (int j = 0; j < 2; j++) wmma::fill_fragment(acc[i][j], 0.0f);

    load_tiles(As[0], Bs[0], m0, n0, 0, tid);
    cp_commit();

    const int NT = KK / 32;
    for (int t = 0; t < NT; t++) {
        const int buf = t & 1;
        if (t + 1 < NT) {
            load_tiles(As[buf ^ 1], Bs[buf ^ 1], m0, n0, (t + 1) * 32, tid);
            cp_commit();
            cp_wait<1>();
        } else {
            cp_wait<0>();
        }
        __syncthreads();

        const float* Asb = As[buf];
        const float* Bsb = Bs[buf];
        #pragma unroll
        for (int kk = 0; kk < 32; kk += 8) {
            wmma::fragment<wmma::matrix_a, 16, 16, 8, wmma::precision::tf32, wmma::row_major> a[2];
            wmma::fragment<wmma::matrix_b, 16, 16, 8, wmma::precision::tf32, wmma::row_major> b[2];
            #pragma unroll
            for (int i = 0; i < 2; i++)
                wmma::load_matrix_sync(a[i], Asb + (wm * 32 + i * 16) * LDA + kk, LDA);
            #pragma unroll
            for (int j = 0; j < 2; j++)
                wmma::load_matrix_sync(b[j], Bsb + kk * LDB + wn * 32 + j * 16, LDB);
            #pragma unroll
            for (int i = 0; i < 2; i++)
                #pragma unroll
                for (int j = 0; j < 2; j++)
                    wmma::mma_sync(acc[i][j], a[i], b[j], acc[i][j]);
        }
        __syncthreads();
    }

    float* Cs = sm;
    #pragma unroll
    for (int i = 0; i < 2; i++)
        #pragma unroll
        for (int j = 0; j < 2; j++)
            wmma::store_matrix_sync(Cs + (size_t)(wm * 32 + i * 16) * 128 + wn * 32 + j * 16,
                                    acc[i][j], 128, wmma::mem_row_major);
    __syncthreads();

    #pragma unroll
    for (int i = 0; i < 8; i++) {
        int idx = tid + i * 512;
        int row = idx >> 5;
        int c4 = (idx & 31) << 2;
        float4 c = *(const float4*)(Cs + row * 128 + c4);
        c.x += bias[n0 + c4 + 0];
        c.y += bias[n0 + c4 + 1];
        c.z += bias[n0 + c4 + 2];
        c.w += bias[n0 + c4 + 3];
        *(float4*)(g_qkv + (size_t)(m0 + row) * N3 + n0 + c4) = c;
    }
}

// ---------------------------------------------------------------------------
// Kernel 2: RoPE + tf32 round. Writes g_q (scaled) / g_k / g_v in [b][h][s][d].
// ---------------------------------------------------------------------------
__global__ __launch_bounds__(256) void rope_round() {
    const int s0 = blockIdx.x * 16;
    const int h = blockIdx.y;
    const int zz = blockIdx.z;      // b*3 + which (0=q, 1=k, 2=v)
    const int b = zz / 3;
    const int which = zz % 3;

    const float* src = g_qkv + ((size_t)(b * SS + s0)) * N3 + which * EE + h * DD;
    float* dst = (which == 0 ? g_q : which == 1 ? g_k : g_v)
                 + ((size_t)(b * HH + h) * SS + s0) * DD;

    #pragma unroll
    for (int i = 0; i < 8; i++) {
        int e = threadIdx.x + i * 256;     // 2048 = 16 s x 128 d
        int sl = e >> 7, d = e & 127;
        float u = src[(size_t)sl * N3 + d];
        float r;
        if (which == 2) {
            r = u;
        } else {
            float w = src[(size_t)sl * N3 + (d ^ 64)];
            float rh = (d < 64) ? -w : w;
            float t = (float)((s0 + sl) * 128 + d);
            float sv, cv;
            sincosf(t, &sv, &cv);
            r = u * cv + rh * sv;
            if (which == 0) r *= 0.08838834764831845f;   // 1/sqrt(128)
        }
        dst[(size_t)sl * DD + d] = tf32_rn(r);
    }
}

// ---------------------------------------------------------------------------
// Kernel 3: flash attention via tf32 mma.sync (m16n8k8).
// 512 threads (16 warps: wm=wid&3 row-block, wn=wid>>2 col-block).
// BM=128, BN=128, D=128. Per warp: S 32mx32n, O 32mx32d. Online softmax with
// register-resident stats (documented mma lane mapping). P overwrites K smem.
// smem: Qs 128x132 + KP 128x132 + Vs 128x136 + stats 1024 = 208896 B.
// ---------------------------------------------------------------------------
#define LDQ 132
#define LDK 132
#define LDV 136
#define ATT_SMEM ((128*LDQ + 128*LDK + 128*LDV + 1024) * 4)

__global__ __launch_bounds__(512, 1) void attn_tc(float* __restrict__ out) {
    extern __shared__ float sm[];
    float* Qs = sm;                        // 128*132
    float* KP = Qs + 128 * LDQ;            // K tile, later P tile
    float* Vs = KP + 128 * LDK;            // 128*136
    float* mpart = Vs + 128 * LDV;         // 4*128
    float* lpart = mpart + 512;            // 4*128

    const int tid = threadIdx.x;
    const int wid = tid >> 5;
    const int lane = tid & 31;
    const int wm = wid & 3;
    const int wn = wid >> 2;
    const int g = lane >> 2;      // group id (row within 8)
    const int q = lane & 3;       // thread in quad
    const int rbase = wm * 32;
    const int s0 = blockIdx.x * 128;
    const int h = blockIdx.y;
    const int b = blockIdx.z;

    const float* qg = g_q + ((size_t)(b * HH + h) * SS + s0) * DD;
    const float* kg = g_k + ((size_t)(b * HH + h) * SS) * DD;
    const float* vg = g_v + ((size_t)(b * HH + h) * SS) * DD;

    // Load Q tile (group 1 of 3), then K0, V0
    #pragma unroll
    for (int i = 0; i < 8; i++) {
        int idx = tid + i * 512;           // 4096 float4
        int row = idx >> 5;
        int c = (idx & 31) << 2;
        cp_async16(Qs + row * LDQ + c, qg + (size_t)row * DD + c);
    }
    cp_commit();
    #pragma unroll
    for (int i = 0; i < 8; i++) {
        int idx = tid + i * 512;
        int row = idx >> 5;
        int c = (idx & 31) << 2;
        cp_async16(KP + row * LDK + c, kg + (size_t)row * DD + c);
    }
    cp_commit();
    #pragma unroll
    for (int i = 0; i < 8; i++) {
        int idx = tid + i * 512;
        int row = idx >> 5;
        int c = (idx & 31) << 2;
        cp_async16(Vs + row * LDV + c, vg + (size_t)row * DD + c);
    }
    cp_commit();

    float o[2][4][4];
    #pragma unroll
    for (int mf = 0; mf < 2; mf++)
        #pragma unroll
        for (int nf = 0; nf < 4; nf++)
            #pragma unroll
            for (int e = 0; e < 4; e++) o[mf][nf][e] = 0.0f;
    float m_run[2][2] = {{-1e30f, -1e30f}, {-1e30f, -1e30f}};
    float l_run[2][2] = {{0.0f, 0.0f}, {0.0f, 0.0f}};

    for (int t = 0; t < SS / 128; t++) {
        cp_wait<1>();          // Q(+prev) and K ready; V may be in flight
        __syncthreads();

        // ---- S = Q K^T (tile) ----
        float s_[2][4][4];
        #pragma unroll
        for (int mf = 0; mf < 2; mf++)
            #pragma unroll
            for (int nf = 0; nf < 4; nf++)
                #pragma unroll
                for (int e = 0; e < 4; e++) s_[mf][nf][e] = 0.0f;

        #pragma unroll
        for (int kk = 0; kk < 16; kk++) {
            unsigned a[2][4];
            #pragma unroll
            for (int mf = 0; mf < 2; mf++) {
                const float* qp = Qs + (rbase + mf * 16 + g) * LDQ + kk * 8 + q;
                a[mf][0] = __float_as_uint(qp[0]);
                a[mf][1] = __float_as_uint(qp[8 * LDQ]);
                a[mf][2] = __float_as_uint(qp[4]);
                a[mf][3] = __float_as_uint(qp[8 * LDQ + 4]);
            }
            #pragma unroll
            for (int nf = 0; nf < 4; nf++) {
                const float* kp = KP + (wn * 32 + nf * 8 + g) * LDK + kk * 8 + q;
                unsigned bf[2] = { __float_as_uint(kp[0]), __float_as_uint(kp[4]) };
                mma_tf32(s_[0][nf], a[0], bf);
                mma_tf32(s_[1][nf], a[1], bf);
            }
        }

        // ---- local row max + quad reduce ----
        float lm[2][2] = {{-1e30f, -1e30f}, {-1e30f, -1e30f}};
        #pragma unroll
        for (int mf = 0; mf < 2; mf++)
            #pragma unroll
            for (int nf = 0; nf < 4; nf++) {
                lm[mf][0] = fmaxf(lm[mf][0], fmaxf(s_[mf][nf][0], s_[mf][nf][1]));
                lm[mf][1] = fmaxf(lm[mf][1], fmaxf(s_[mf][nf][2], s_[mf][nf][3]));
            }
        #pragma unroll
        for (int off = 1; off <= 2; off <<= 1)
            #pragma unroll
            for (int mf = 0; mf < 2; mf++)
                #pragma unroll
                for (int hf = 0; hf < 2; hf++)
                    lm[mf][hf] = fmaxf(lm[mf][hf],
                                       __shfl_xor_sync(0xffffffffu, lm[mf][hf], off));
        if (q == 0) {
            #pragma unroll
            for (int mf = 0; mf < 2; mf++)
                #pragma unroll
                for (int hf = 0; hf < 2; hf++)
                    mpart[wn * 128 + rbase + mf * 16 + g + hf * 8] = lm[mf][hf];
        }
        __syncthreads();   // barrier 1: maxes visible; K reads all done

        // ---- joint max, alpha, exp, P store (into KP), local sums ----
        float mnew[2][2], al[2][2];
        #pragma unroll
        for (int mf = 0; mf < 2; mf++)
            #pragma unroll
            for (int hf = 0; hf < 2; hf++) {
                int r = rbase + mf * 16 + g + hf * 8;
                float mv = fmaxf(fmaxf(mpart[r], mpart[128 + r]),
                                 fmaxf(mpart[256 + r], mpart[384 + r]));
                float mn = fmaxf(m_run[mf][hf], mv);
                al[mf][hf] = __expf(m_run[mf][hf] - mn);
                m_run[mf][hf] = mn;
                mnew[mf][hf] = mn;
            }
        float ls[2][2] = {{0.0f, 0.0f}, {0.0f, 0.0f}};
        #pragma unroll
        for (int mf = 0; mf < 2; mf++)
            #pragma unroll
            for (int nf = 0; nf < 4; nf++) {
                float p0 = __expf(s_[mf][nf][0] - mnew[mf][0]);
                float p1 = __expf(s_[mf][nf][1] - mnew[mf][0]);
                float p2 = __expf(s_[mf][nf][2] - mnew[mf][1]);
                float p3 = __expf(s_[mf][nf][3] - mnew[mf][1]);
                ls[mf][0] += p0 + p1;
                ls[mf][1] += p2 + p3;
                int col = wn * 32 + nf * 8 + q * 2;
                float2 w0 = { tf32_rn(p0), tf32_rn(p1) };
                float2 w1 = { tf32_rn(p2), tf32_rn(p3) };
                *(float2*)(KP + (rbase + mf * 16 + g) * LDK + col) = w0;
                *(float2*)(KP + (rbase + mf * 16 + g + 8) * LDK + col) = w1;
            }
        #pragma unroll
        for (int off = 1; off <= 2; off <<= 1)
            #pragma unroll
            for (int mf = 0; mf < 2; mf++)
                #pragma unroll
                for (int hf = 0; hf < 2; hf++)
                    ls[mf][hf] += __shfl_xor_sync(0xffffffffu, ls[mf][hf], off);
        if (q == 0) {
            #pragma unroll
            for (int mf = 0; mf < 2; mf++)
                #pragma unroll
                for (int hf = 0; hf < 2; hf++)
                    lpart[wn * 128 + rbase + mf * 16 + g + hf * 8] = ls[mf][hf];
        }
        cp_wait<0>();      // V copies (own) complete before barrier
        __syncthreads();   // barrier 2: P + sums + V visible to all

        // ---- l update, O rescale ----
        #pragma unroll
        for (int mf = 0; mf < 2; mf++)
            #pragma unroll
            for (int hf = 0; hf < 2; hf++) {
                int r = rbase + mf * 16 + g + hf * 8;
                float lsum = lpart[r] + lpart[128 + r] + lpart[256 + r] + lpart[384 + r];
                l_run[mf][hf] = l_run[mf][hf] * al[mf][hf] + lsum;
            }
        #pragma unroll
        for (int mf = 0; mf < 2; mf++)
            #pragma unroll
            for (int nf = 0; nf < 4; nf++) {
                o[mf][nf][0] *= al[mf][0];
                o[mf][nf][1] *= al[mf][0];
                o[mf][nf][2] *= al[mf][1];
                o[mf][nf][3] *= al[mf][1];
            }

        // ---- O += P V ----
        #pragma unroll
        for (int kk = 0; kk < 16; kk++) {
            unsigned a[2][4];
            #pragma unroll
            for (int mf = 0; mf < 2; mf++) {
                const float* pp = KP + (rbase + mf * 16 + g) * LDK + kk * 8 + q;
                a[mf][0] = __float_as_uint(pp[0]);
                a[mf][1] = __float_as_uint(pp[8 * LDK]);
                a[mf][2] = __float_as_uint(pp[4]);
                a[mf][3] = __float_as_uint(pp[8 * LDK + 4]);
            }
            #pragma unroll
            for (int nf = 0; nf < 4; nf++) {
                const float* vp = Vs + (kk * 8 + q) * LDV + wn * 32 + nf * 8 + g;
                unsigned bf[2] = { __float_as_uint(vp[0]), __float_as_uint(vp[4 * LDV]) };
                mma_tf32(o[0][nf], a[0], bf);
                mma_tf32(o[1][nf], a[1], bf);
            }
        }
        __syncthreads();   // barrier 3: P reads done before next K overwrite

        if (t + 1 < SS / 128) {
            const float* kn = kg + (size_t)(t + 1) * 128 * DD;
            const float* vn = vg + (size_t)(t + 1) * 128 * DD;
            #pragma unroll
            for (int i = 0; i < 8; i++) {
                int idx = tid + i * 512;
                int row = idx >> 5;
                int c = (idx & 31) << 2;
                cp_async16(KP + row * LDK + c, kn + (size_t)row * DD + c);
            }
            cp_commit();
            #pragma unroll
            for (int i = 0; i < 8; i++) {
                int idx = tid + i * 512;
                int row = idx >> 5;
                int c = (idx & 31) << 2;
                cp_async16(Vs + row * LDV + c, vn + (size_t)row * DD + c);
            }
            cp_commit();
        }
    }

    // ---- epilogue: normalize, write out[b][s][h][d] ----
    float inv[2][2];
    #pragma unroll
    for (int mf = 0; mf < 2; mf++)
        #pragma unroll
        for (int hf = 0; hf < 2; hf++)
            inv[mf][hf] = 1.0f / l_run[mf][hf];

    #pragma unroll
    for (int mf = 0; mf < 2; mf++)
        #pragma unroll
        for (int nf = 0; nf < 4; nf++) {
            int col = wn * 32 + nf * 8 + q * 2;
            int row0 = s0 + rbase + mf * 16 + g;
            float2 w0 = { o[mf][nf][0] * inv[mf][0], o[mf][nf][1] * inv[mf][0] };
            float2 w1 = { o[mf][nf][2] * inv[mf][1], o[mf][nf][3] * inv[mf][1] };
            *(float2*)(out + ((size_t)(b * SS + row0) * HH + h) * DD + col) = w0;
            *(float2*)(out + ((size_t)(b * SS + row0 + 8) * HH + h) * DD + col) = w1;
        }
}

// ---------------------------------------------------------------------------
extern "C" void kernel_launch(void* const* d_in, const int* in_sizes, int n_in,
                              void* d_out, int out_size) {
    const float* x    = (const float*)d_in[0];
    const float* W    = (const float*)d_in[1];
    const float* bias = (const float*)d_in[2];
    float* out = (float*)d_out;

    round_x<<<(int)((size_t)MM * KK / 1024), 256>>>(x);
    round_w<<<(int)((size_t)KK * N3 / 1024), 256>>>(W);

    const int gemm_smem = (2 * 128 * LDA + 2 * 32 * LDB) * 4;   // 75776
    cudaFuncSetAttribute(qkv_gemm, cudaFuncAttributeMaxDynamicSharedMemorySize, gemm_smem);
    dim3 g1(N3 / 128, MM / 128);
    qkv_gemm<<<g1, 512, gemm_smem>>>(bias);

    dim3 g2(SS / 16, HH, BB * 3);       // 128 x 16 x 6
    rope_round<<<g2, 256>>>();

    cudaFuncSetAttribute(attn_tc, cudaFuncAttributeMaxDynamicSharedMemorySize, ATT_SMEM);
    dim3 g3(SS / 128, HH, BB);          // 16 x 16 x 2
    attn_tc<<<g3, 512, ATT_SMEM>>>(out);
}

// round 7
// speedup vs baseline: 6.5845x; 2.5991x over previous
#include <cuda_runtime.h>
#include <mma.h>
#include <math.h>
#include <stdint.h>
#include <cuda_fp16.h>

using namespace nvcuda;

#define BB 2
#define SS 2048
#define EE 2048
#define HH 16
#define DD 128
#define N3 6144            // 3*EE
#define MM (BB*SS)         // 4096
#define KK EE              // 2048

#define LDAH 40            // GEMM A smem row stride (halves)
#define LDBH 136           // GEMM B smem row stride (halves)

// Scratch (static device globals — allowed; no runtime allocation)
__device__ float  g_qkv[(size_t)MM * N3];           // raw qkv fp32, [b*S+s][3*E]
__device__ __half g_xh [(size_t)MM * KK];           // X in fp16 (RN)
__device__ __half g_wh [(size_t)KK * N3];           // W in fp16 (RN)
__device__ __half g_qh [(size_t)BB * HH * SS * DD]; // Q roped+scaled, [b][h][s][d]
__device__ __half g_kh [(size_t)BB * HH * SS * DD]; // K roped,        [b][h][s][d]
__device__ __half g_vt [(size_t)BB * HH * DD * SS]; // V transposed,   [b][h][d][s]

// ---------------------------------------------------------------------------
// Helpers
// ---------------------------------------------------------------------------
__device__ __forceinline__ void cp_async16(void* dst_smem, const void* src_gmem) {
    unsigned int dst = (unsigned int)__cvta_generic_to_shared(dst_smem);
    asm volatile("cp.async.cg.shared.global [%0], [%1], 16;\n" :: "r"(dst), "l"(src_gmem));
}
__device__ __forceinline__ void cp_commit() {
    asm volatile("cp.async.commit_group;\n" ::: "memory");
}
template <int N>
__device__ __forceinline__ void cp_wait() {
    asm volatile("cp.async.wait_group %0;\n" :: "n"(N) : "memory");
}
// mma.sync m16n8k16 fp16 -> fp32, documented lane mapping
__device__ __forceinline__ void mma_f16(float* c, const unsigned* a, const unsigned* b) {
    asm volatile(
        "mma.sync.aligned.m16n8k16.row.col.f32.f16.f16.f32 "
        "{%0,%1,%2,%3}, {%4,%5,%6,%7}, {%8,%9}, {%0,%1,%2,%3};"
        : "+f"(c[0]), "+f"(c[1]), "+f"(c[2]), "+f"(c[3])
        : "r"(a[0]), "r"(a[1]), "r"(a[2]), "r"(a[3]), "r"(b[0]), "r"(b[1]));
}

// ---------------------------------------------------------------------------
// Prep kernels: convert X / W to fp16 (RN).  8 floats -> 8 halves per thread.
// ---------------------------------------------------------------------------
__global__ __launch_bounds__(256) void cvt_x(const float* __restrict__ X) {
    size_t i = ((size_t)blockIdx.x * 256 + threadIdx.x) * 8;
    float4 v0 = *(const float4*)(X + i);
    float4 v1 = *(const float4*)(X + i + 4);
    __half2 h[4] = { __floats2half2_rn(v0.x, v0.y), __floats2half2_rn(v0.z, v0.w),
                     __floats2half2_rn(v1.x, v1.y), __floats2half2_rn(v1.z, v1.w) };
    *(uint4*)(g_xh + i) = *(uint4*)h;
}
__global__ __launch_bounds__(256) void cvt_w(const float* __restrict__ W) {
    size_t i = ((size_t)blockIdx.x * 256 + threadIdx.x) * 8;
    float4 v0 = *(const float4*)(W + i);
    float4 v1 = *(const float4*)(W + i + 4);
    __half2 h[4] = { __floats2half2_rn(v0.x, v0.y), __floats2half2_rn(v0.z, v0.w),
                     __floats2half2_rn(v1.x, v1.y), __floats2half2_rn(v1.z, v1.w) };
    *(uint4*)(g_wh + i) = *(uint4*)h;
}

// ---------------------------------------------------------------------------
// Kernel 1: QKV GEMM (fp16 wmma 16x16x16, fp32 accum).
// 128x128 block tile, BK=32, 512 threads (16 warps, 4x4), warp tile 32x32.
// Double-buffered cp.async. Bias in fp32 smem-staged epilogue.
// smem: stages 2*(128*40 + 32*136)*2 = 37888 B; epilogue Cs 64 KB -> 65536 B.
// ---------------------------------------------------------------------------
#define GEMM_SMEM 65536

__device__ __forceinline__ void load_tiles(__half* As, __half* Bs,
                                           int m0, int n0, int kt, int tid) {
    {   // A: 128 rows x 32 halves = 512 chunks of 16B
        int row = tid >> 2;
        int c8 = (tid & 3) << 3;
        cp_async16(As + row * LDAH + c8, g_xh + (size_t)(m0 + row) * KK + kt + c8);
    }
    {   // B: 32 rows x 128 halves = 512 chunks of 16B
        int row = tid >> 4;
        int c8 = (tid & 15) << 3;
        cp_async16(Bs + row * LDBH + c8, g_wh + (size_t)(kt + row) * N3 + n0 + c8);
    }
}

__global__ __launch_bounds__(512) void qkv_gemm(const float* __restrict__ bias) {
    extern __shared__ char smraw[];
    __half* As[2] = { (__half*)smraw, (__half*)smraw + 128 * LDAH };
    __half* Bs[2] = { (__half*)smraw + 2 * 128 * LDAH,
                      (__half*)smraw + 2 * 128 * LDAH + 32 * LDBH };

    const int tid = threadIdx.x;
    const int wid = tid >> 5;
    const int wm = wid & 3;
    const int wn = wid >> 2;
    const int m0 = blockIdx.y * 128;
    const int n0 = blockIdx.x * 128;

    wmma::fragment<wmma::accumulator, 16, 16, 16, float> acc[2][2];
    #pragma unroll
    for (int i = 0; i < 2; i++)
        #pragma unroll
        for (int j = 0; j < 2; j++) wmma::fill_fragment(acc[i][j], 0.0f);

    load_tiles(As[0], Bs[0], m0, n0, 0, tid);
    cp_commit();

    const int NT = KK / 32;
    for (int t = 0; t < NT; t++) {
        const int buf = t & 1;
        if (t + 1 < NT) {
            load_tiles(As[buf ^ 1], Bs[buf ^ 1], m0, n0, (t + 1) * 32, tid);
            cp_commit();
            cp_wait<1>();
        } else {
            cp_wait<0>();
        }
        __syncthreads();

        const __half* Asb = As[buf];
        const __half* Bsb = Bs[buf];
        #pragma unroll
        for (int kk = 0; kk < 32; kk += 16) {
            wmma::fragment<wmma::matrix_a, 16, 16, 16, __half, wmma::row_major> a[2];
            wmma::fragment<wmma::matrix_b, 16, 16, 16, __half, wmma::row_major> b[2];
            #pragma unroll
            for (int i = 0; i < 2; i++)
                wmma::load_matrix_sync(a[i], Asb + (wm * 32 + i * 16) * LDAH + kk, LDAH);
            #pragma unroll
            for (int j = 0; j < 2; j++)
                wmma::load_matrix_sync(b[j], Bsb + kk * LDBH + wn * 32 + j * 16, LDBH);
            #pragma unroll
            for (int i = 0; i < 2; i++)
                #pragma unroll
                for (int j = 0; j < 2; j++)
                    wmma::mma_sync(acc[i][j], a[i], b[j], acc[i][j]);
        }
        __syncthreads();
    }

    float* Cs = (float*)smraw;
    #pragma unroll
    for (int i = 0; i < 2; i++)
        #pragma unroll
        for (int j = 0; j < 2; j++)
            wmma::store_matrix_sync(Cs + (size_t)(wm * 32 + i * 16) * 128 + wn * 32 + j * 16,
                                    acc[i][j], 128, wmma::mem_row_major);
    __syncthreads();

    #pragma unroll
    for (int i = 0; i < 8; i++) {
        int idx = tid + i * 512;
        int row = idx >> 5;
        int c4 = (idx & 31) << 2;
        float4 c = *(const float4*)(Cs + row * 128 + c4);
        c.x += bias[n0 + c4 + 0];
        c.y += bias[n0 + c4 + 1];
        c.z += bias[n0 + c4 + 2];
        c.w += bias[n0 + c4 + 3];
        *(float4*)(g_qkv + (size_t)(m0 + row) * N3 + n0 + c4) = c;
    }
}

// ---------------------------------------------------------------------------
// Kernel 2: RoPE + fp16 round for Q (scaled) and K.  [b][h][s][d] half.
// ---------------------------------------------------------------------------
__global__ __launch_bounds__(256) void rope_qk() {
    const int s0 = blockIdx.x * 16;
    const int h = blockIdx.y;
    const int zz = blockIdx.z;      // b*2 + which (0=q, 1=k)
    const int b = zz >> 1;
    const int which = zz & 1;

    const float* src = g_qkv + ((size_t)(b * SS + s0)) * N3 + which * EE + h * DD;
    __half* dst = (which == 0 ? g_qh : g_kh) + ((size_t)(b * HH + h) * SS + s0) * DD;

    #pragma unroll
    for (int i = 0; i < 8; i++) {
        int e = threadIdx.x + i * 256;     // 2048 = 16 s x 128 d
        int sl = e >> 7, d = e & 127;
        float u = src[(size_t)sl * N3 + d];
        float w = src[(size_t)sl * N3 + (d ^ 64)];
        float rh = (d < 64) ? -w : w;
        float t = (float)((s0 + sl) * 128 + d);
        float sv, cv;
        sincosf(t, &sv, &cv);
        float r = u * cv + rh * sv;
        if (which == 0) r *= 0.08838834764831845f;   // 1/sqrt(128)
        dst[(size_t)sl * DD + d] = __float2half_rn(r);
    }
}

// ---------------------------------------------------------------------------
// Kernel 2b: V transpose + fp16 round.  g_qkv V slice -> g_vt [b][h][d][s].
// 64 s x 128 d tile through padded smem.
// ---------------------------------------------------------------------------
__global__ __launch_bounds__(256) void v_trans() {
    __shared__ __half tile[64][130];
    const int s0 = blockIdx.x * 64;
    const int h = blockIdx.y;
    const int b = blockIdx.z;

    const float* src = g_qkv + ((size_t)(b * SS + s0)) * N3 + 2 * EE + h * DD;
    #pragma unroll
    for (int i = 0; i < 32; i++) {
        int e = threadIdx.x + i * 256;     // 8192 = 64 s x 128 d
        int sl = e >> 7, d = e & 127;
        tile[sl][d] = __float2half_rn(src[(size_t)sl * N3 + d]);
    }
    __syncthreads();

    __half* dst = g_vt + ((size_t)(b * HH + h) * DD) * SS + s0;
    #pragma unroll
    for (int i = 0; i < 32; i++) {
        int e = threadIdx.x + i * 256;     // d = e>>6, sl = e&63
        int d = e >> 6, sl = e & 63;
        dst[(size_t)d * SS + sl] = tile[sl][d];
    }
}

// ---------------------------------------------------------------------------
// Kernel 3: flash attention via fp16 mma.sync (m16n8k16, fp32 accum).
// 512 threads (16 warps: wm row-block, wn col-block). BM=BN=128, D=128.
// P (half) overwrites K smem. V pre-transposed -> contiguous B fragments.
// smem: Qs/KP/Vt 128x136 halves each + fp32 stats = 108544 B.
// ---------------------------------------------------------------------------
#define LDQH2 136
#define ATT_SMEM (3 * 128 * LDQH2 * 2 + 1024 * 4)

__global__ __launch_bounds__(512, 1) void attn_tc(float* __restrict__ out) {
    extern __shared__ char smraw[];
    __half* Qs = (__half*)smraw;             // [128][136]
    __half* KP = Qs + 128 * LDQH2;           // K tile, later P tile
    __half* Vt = KP + 128 * LDQH2;           // V^T tile: [d][s] 128x136
    float* mpart = (float*)(Vt + 128 * LDQH2);   // 4*128
    float* lpart = mpart + 512;                  // 4*128

    const int tid = threadIdx.x;
    const int wid = tid >> 5;
    const int lane = tid & 31;
    const int wm = wid & 3;
    const int wn = wid >> 2;
    const int g = lane >> 2;
    const int q = lane & 3;
    const int rbase = wm * 32;
    const int s0 = blockIdx.x * 128;
    const int h = blockIdx.y;
    const int b = blockIdx.z;

    const __half* qg = g_qh + ((size_t)(b * HH + h) * SS + s0) * DD;
    const __half* kg = g_kh + ((size_t)(b * HH + h) * SS) * DD;
    const __half* vtg = g_vt + ((size_t)(b * HH + h) * DD) * SS;

    // Load Q tile, K0, V0 (3 cp groups)
    #pragma unroll
    for (int i = 0; i < 4; i++) {
        int idx = tid + i * 512;             // 2048 chunks of 8 halves
        int row = idx >> 4;
        int c8 = (idx & 15) << 3;
        cp_async16(Qs + row * LDQH2 + c8, qg + (size_t)row * DD + c8);
    }
    cp_commit();
    #pragma unroll
    for (int i = 0; i < 4; i++) {
        int idx = tid + i * 512;
        int row = idx >> 4;
        int c8 = (idx & 15) << 3;
        cp_async16(KP + row * LDQH2 + c8, kg + (size_t)row * DD + c8);
    }
    cp_commit();
    #pragma unroll
    for (int i = 0; i < 4; i++) {
        int idx = tid + i * 512;
        int row = idx >> 4;                  // d index
        int c8 = (idx & 15) << 3;            // s within tile
        cp_async16(Vt + row * LDQH2 + c8, vtg + (size_t)row * SS + c8);
    }
    cp_commit();

    float o[2][4][4];
    #pragma unroll
    for (int mf = 0; mf < 2; mf++)
        #pragma unroll
        for (int nf = 0; nf < 4; nf++)
            #pragma unroll
            for (int e = 0; e < 4; e++) o[mf][nf][e] = 0.0f;
    float m_run[2][2] = {{-1e30f, -1e30f}, {-1e30f, -1e30f}};
    float l_run[2][2] = {{0.0f, 0.0f}, {0.0f, 0.0f}};

    for (int t = 0; t < SS / 128; t++) {
        cp_wait<1>();          // Q + K ready; V may be in flight
        __syncthreads();

        // ---- S = Q K^T ----
        float s_[2][4][4];
        #pragma unroll
        for (int mf = 0; mf < 2; mf++)
            #pragma unroll
            for (int nf = 0; nf < 4; nf++)
                #pragma unroll
                for (int e = 0; e < 4; e++) s_[mf][nf][e] = 0.0f;

        #pragma unroll
        for (int kk = 0; kk < 8; kk++) {
            unsigned a[2][4];
            #pragma unroll
            for (int mf = 0; mf < 2; mf++) {
                const __half* qp = Qs + (rbase + mf * 16 + g) * LDQH2 + kk * 16 + q * 2;
                a[mf][0] = *(const unsigned*)(qp);
                a[mf][1] = *(const unsigned*)(qp + 8 * LDQH2);
                a[mf][2] = *(const unsigned*)(qp + 8);
                a[mf][3] = *(const unsigned*)(qp + 8 * LDQH2 + 8);
            }
            #pragma unroll
            for (int nf = 0; nf < 4; nf++) {
                const __half* kp = KP + (wn * 32 + nf * 8 + g) * LDQH2 + kk * 16 + q * 2;
                unsigned bf[2] = { *(const unsigned*)(kp), *(const unsigned*)(kp + 8) };
                mma_f16(s_[0][nf], a[0], bf);
                mma_f16(s_[1][nf], a[1], bf);
            }
        }

        // ---- local row max + quad reduce ----
        float lm[2][2] = {{-1e30f, -1e30f}, {-1e30f, -1e30f}};
        #pragma unroll
        for (int mf = 0; mf < 2; mf++)
            #pragma unroll
            for (int nf = 0; nf < 4; nf++) {
                lm[mf][0] = fmaxf(lm[mf][0], fmaxf(s_[mf][nf][0], s_[mf][nf][1]));
                lm[mf][1] = fmaxf(lm[mf][1], fmaxf(s_[mf][nf][2], s_[mf][nf][3]));
            }
        #pragma unroll
        for (int off = 1; off <= 2; off <<= 1)
            #pragma unroll
            for (int mf = 0; mf < 2; mf++)
                #pragma unroll
                for (int hf = 0; hf < 2; hf++)
                    lm[mf][hf] = fmaxf(lm[mf][hf],
                                       __shfl_xor_sync(0xffffffffu, lm[mf][hf], off));
        if (q == 0) {
            #pragma unroll
            for (int mf = 0; mf < 2; mf++)
                #pragma unroll
                for (int hf = 0; hf < 2; hf++)
                    mpart[wn * 128 + rbase + mf * 16 + g + hf * 8] = lm[mf][hf];
        }
        __syncthreads();   // barrier 1: maxes visible; K reads all done

        // ---- joint max, alpha, exp, P store (half, into KP), local sums ----
        float mnew[2][2], al[2][2];
        #pragma unroll
        for (int mf = 0; mf < 2; mf++)
            #pragma unroll
            for (int hf = 0; hf < 2; hf++) {
                int r = rbase + mf * 16 + g + hf * 8;
                float mv = fmaxf(fmaxf(mpart[r], mpart[128 + r]),
                                 fmaxf(mpart[256 + r], mpart[384 + r]));
                float mn = fmaxf(m_run[mf][hf], mv);
                al[mf][hf] = __expf(m_run[mf][hf] - mn);
                m_run[mf][hf] = mn;
                mnew[mf][hf] = mn;
            }
        float ls[2][2] = {{0.0f, 0.0f}, {0.0f, 0.0f}};
        #pragma unroll
        for (int mf = 0; mf < 2; mf++)
            #pragma unroll
            for (int nf = 0; nf < 4; nf++) {
                float p0 = __expf(s_[mf][nf][0] - mnew[mf][0]);
                float p1 = __expf(s_[mf][nf][1] - mnew[mf][0]);
                float p2 = __expf(s_[mf][nf][2] - mnew[mf][1]);
                float p3 = __expf(s_[mf][nf][3] - mnew[mf][1]);
                ls[mf][0] += p0 + p1;
                ls[mf][1] += p2 + p3;
                int col = wn * 32 + nf * 8 + q * 2;
                *(__half2*)(KP + (rbase + mf * 16 + g) * LDQH2 + col) =
                    __floats2half2_rn(p0, p1);
                *(__half2*)(KP + (rbase + mf * 16 + g + 8) * LDQH2 + col) =
                    __floats2half2_rn(p2, p3);
            }
        #pragma unroll
        for (int off = 1; off <= 2; off <<= 1)
            #pragma unroll
            for (int mf = 0; mf < 2; mf++)
                #pragma unroll
                for (int hf = 0; hf < 2; hf++)
                    ls[mf][hf] += __shfl_xor_sync(0xffffffffu, ls[mf][hf], off);
        if (q == 0) {
            #pragma unroll
            for (int mf = 0; mf < 2; mf++)
                #pragma unroll
                for (int hf = 0; hf < 2; hf++)
                    lpart[wn * 128 + rbase + mf * 16 + g + hf * 8] = ls[mf][hf];
        }
        cp_wait<0>();      // V complete before barrier
        __syncthreads();   // barrier 2: P + sums + V visible

        // ---- l update, O rescale ----
        #pragma unroll
        for (int mf = 0; mf < 2; mf++)
            #pragma unroll
            for (int hf = 0; hf < 2; hf++) {
                int r = rbase + mf * 16 + g + hf * 8;
                float lsum = lpart[r] + lpart[128 + r] + lpart[256 + r] + lpart[384 + r];
                l_run[mf][hf] = l_run[mf][hf] * al[mf][hf] + lsum;
            }
        #pragma unroll
        for (int mf = 0; mf < 2; mf++)
            #pragma unroll
            for (int nf = 0; nf < 4; nf++) {
                o[mf][nf][0] *= al[mf][0];
                o[mf][nf][1] *= al[mf][0];
                o[mf][nf][2] *= al[mf][1];
                o[mf][nf][3] *= al[mf][1];
            }

        // ---- O += P V  (B fragments from Vt, contiguous) ----
        #pragma unroll
        for (int kk = 0; kk < 8; kk++) {
            unsigned a[2][4];
            #pragma unroll
            for (int mf = 0; mf < 2; mf++) {
                const __half* pp = KP + (rbase + mf * 16 + g) * LDQH2 + kk * 16 + q * 2;
                a[mf][0] = *(const unsigned*)(pp);
                a[mf][1] = *(const unsigned*)(pp + 8 * LDQH2);
                a[mf][2] = *(const unsigned*)(pp + 8);
                a[mf][3] = *(const unsigned*)(pp + 8 * LDQH2 + 8);
            }
            #pragma unroll
            for (int nf = 0; nf < 4; nf++) {
                const __half* vp = Vt + (wn * 32 + nf * 8 + g) * LDQH2 + kk * 16 + q * 2;
                unsigned bf[2] = { *(const unsigned*)(vp), *(const unsigned*)(vp + 8) };
                mma_f16(o[0][nf], a[0], bf);
                mma_f16(o[1][nf], a[1], bf);
            }
        }
        __syncthreads();   // barrier 3: P reads done before next K overwrite

        if (t + 1 < SS / 128) {
            const __half* kn = kg + (size_t)(t + 1) * 128 * DD;
            const __half* vn = vtg + (size_t)(t + 1) * 128;
            #pragma unroll
            for (int i = 0; i < 4; i++) {
                int idx = tid + i * 512;
                int row = idx >> 4;
                int c8 = (idx & 15) << 3;
                cp_async16(KP + row * LDQH2 + c8, kn + (size_t)row * DD + c8);
            }
            cp_commit();
            #pragma unroll
            for (int i = 0; i < 4; i++) {
                int idx = tid + i * 512;
                int row = idx >> 4;
                int c8 = (idx & 15) << 3;
                cp_async16(Vt + row * LDQH2 + c8, vn + (size_t)row * SS + c8);
            }
            cp_commit();
        }
    }

    // ---- epilogue: normalize, write out[b][s][h][d] fp32 ----
    float inv[2][2];
    #pragma unroll
    for (int mf = 0; mf < 2; mf++)
        #pragma unroll
        for (int hf = 0; hf < 2; hf++)
            inv[mf][hf] = 1.0f / l_run[mf][hf];

    #pragma unroll
    for (int mf = 0; mf < 2; mf++)
        #pragma unroll
        for (int nf = 0; nf < 4; nf++) {
            int col = wn * 32 + nf * 8 + q * 2;
            int row0 = s0 + rbase + mf * 16 + g;
            float2 w0 = { o[mf][nf][0] * inv[mf][0], o[mf][nf][1] * inv[mf][0] };
            float2 w1 = { o[mf][nf][2] * inv[mf][1], o[mf][nf][3] * inv[mf][1] };
            *(float2*)(out + ((size_t)(b * SS + row0) * HH + h) * DD + col) = w0;
            *(float2*)(out + ((size_t)(b * SS + row0 + 8) * HH + h) * DD + col) = w1;
        }
}

// ---------------------------------------------------------------------------
extern "C" void kernel_launch(void* const* d_in, const int* in_sizes, int n_in,
                              void* d_out, int out_size) {
    const float* x    = (const float*)d_in[0];
    const float* W    = (const float*)d_in[1];
    const float* bias = (const float*)d_in[2];
    float* out = (float*)d_out;

    cvt_x<<<(int)((size_t)MM * KK / 2048), 256>>>(x);
    cvt_w<<<(int)((size_t)KK * N3 / 2048), 256>>>(W);

    cudaFuncSetAttribute(qkv_gemm, cudaFuncAttributeMaxDynamicSharedMemorySize, GEMM_SMEM);
    dim3 g1(N3 / 128, MM / 128);
    qkv_gemm<<<g1, 512, GEMM_SMEM>>>(bias);

    dim3 g2(SS / 16, HH, BB * 2);       // q, k
    rope_qk<<<g2, 256>>>();
    dim3 g2b(SS / 64, HH, BB);          // v transpose
    v_trans<<<g2b, 256>>>();

    cudaFuncSetAttribute(attn_tc, cudaFuncAttributeMaxDynamicSharedMemorySize, ATT_SMEM);
    dim3 g3(SS / 128, HH, BB);
    attn_tc<<<g3, 512, ATT_SMEM>>>(out);
}

// round 8
// speedup vs baseline: 7.2166x; 1.0960x over previous
#include <cuda_runtime.h>
#include <mma.h>
#include <math.h>
#include <stdint.h>
#include <cuda_fp16.h>

using namespace nvcuda;

#define BB 2
#define SS 2048
#define EE 2048
#define HH 16
#define DD 128
#define N3 6144            // 3*EE
#define MM (BB*SS)         // 4096
#define KK EE              // 2048

#define LDAH 40            // GEMM A smem row stride (halves)
#define LDBH 136           // GEMM B smem row stride (halves)
#define LDC  132           // GEMM epilogue staging stride (floats)

// Scratch (static device globals — allowed; no runtime allocation)
__device__ __half g_xh [(size_t)MM * KK];           // X in fp16 (RN)
__device__ __half g_wh [(size_t)KK * N3];           // W in fp16 (RN)
__device__ float2 g_sc [(size_t)SS * DD];           // sin/cos table for t = s*128+d
__device__ __half g_qh [(size_t)BB * HH * SS * DD]; // Q roped+scaled, [b][h][s][d]
__device__ __half g_kh [(size_t)BB * HH * SS * DD]; // K roped,        [b][h][s][d]
__device__ __half g_vt [(size_t)BB * HH * DD * SS]; // V transposed,   [b][h][d][s]

// ---------------------------------------------------------------------------
// Helpers
// ---------------------------------------------------------------------------
__device__ __forceinline__ void cp_async16(void* dst_smem, const void* src_gmem) {
    unsigned int dst = (unsigned int)__cvta_generic_to_shared(dst_smem);
    asm volatile("cp.async.cg.shared.global [%0], [%1], 16;\n" :: "r"(dst), "l"(src_gmem));
}
__device__ __forceinline__ void cp_commit() {
    asm volatile("cp.async.commit_group;\n" ::: "memory");
}
template <int N>
__device__ __forceinline__ void cp_wait() {
    asm volatile("cp.async.wait_group %0;\n" :: "n"(N) : "memory");
}
// mma.sync m16n8k16 fp16 -> fp32, documented lane mapping
__device__ __forceinline__ void mma_f16(float* c, const unsigned* a, const unsigned* b) {
    asm volatile(
        "mma.sync.aligned.m16n8k16.row.col.f32.f16.f16.f32 "
        "{%0,%1,%2,%3}, {%4,%5,%6,%7}, {%8,%9}, {%0,%1,%2,%3};"
        : "+f"(c[0]), "+f"(c[1]), "+f"(c[2]), "+f"(c[3])
        : "r"(a[0]), "r"(a[1]), "r"(a[2]), "r"(a[3]), "r"(b[0]), "r"(b[1]));
}

// ---------------------------------------------------------------------------
// Prep kernels
// ---------------------------------------------------------------------------
__global__ __launch_bounds__(256) void cvt_x(const float* __restrict__ X) {
    size_t i = ((size_t)blockIdx.x * 256 + threadIdx.x) * 8;
    float4 v0 = *(const float4*)(X + i);
    float4 v1 = *(const float4*)(X + i + 4);
    __half2 h[4] = { __floats2half2_rn(v0.x, v0.y), __floats2half2_rn(v0.z, v0.w),
                     __floats2half2_rn(v1.x, v1.y), __floats2half2_rn(v1.z, v1.w) };
    *(uint4*)(g_xh + i) = *(uint4*)h;
}
__global__ __launch_bounds__(256) void cvt_w(const float* __restrict__ W) {
    size_t i = ((size_t)blockIdx.x * 256 + threadIdx.x) * 8;
    float4 v0 = *(const float4*)(W + i);
    float4 v1 = *(const float4*)(W + i + 4);
    __half2 h[4] = { __floats2half2_rn(v0.x, v0.y), __floats2half2_rn(v0.z, v0.w),
                     __floats2half2_rn(v1.x, v1.y), __floats2half2_rn(v1.z, v1.w) };
    *(uint4*)(g_wh + i) = *(uint4*)h;
}
// sin/cos table: g_sc[i] = {sin(i), cos(i)} for i = s*128+d (matches reference t)
__global__ __launch_bounds__(256) void sc_table() {
    int i = blockIdx.x * 256 + threadIdx.x;
    float sv, cv;
    sincosf((float)i, &sv, &cv);
    g_sc[i] = make_float2(sv, cv);
}

// ---------------------------------------------------------------------------
// Kernel 1: QKV GEMM (fp16 wmma 16x16x16, fp32 accum) with FUSED epilogue:
// bias + RoPE(+scale) + fp16 round, writing g_qh / g_kh / g_vt directly.
// Each 128-wide n-block is exactly one (q|k|v, head) slice; each 128-row
// m-block lies within one batch. 128x128x32 tiles, 512 threads.
// smem: stages 37888 B; epilogue Cs 128x132 fp32 = 67584 B -> GEMM_SMEM.
// ---------------------------------------------------------------------------
#define GEMM_SMEM 67584

__device__ __forceinline__ void load_tiles(__half* As, __half* Bs,
                                           int m0, int n0, int kt, int tid) {
    {   // A: 128 rows x 32 halves
        int row = tid >> 2;
        int c8 = (tid & 3) << 3;
        cp_async16(As + row * LDAH + c8, g_xh + (size_t)(m0 + row) * KK + kt + c8);
    }
    {   // B: 32 rows x 128 halves
        int row = tid >> 4;
        int c8 = (tid & 15) << 3;
        cp_async16(Bs + row * LDBH + c8, g_wh + (size_t)(kt + row) * N3 + n0 + c8);
    }
}

__global__ __launch_bounds__(512) void qkv_gemm(const float* __restrict__ bias) {
    extern __shared__ char smraw[];
    __half* As[2] = { (__half*)smraw, (__half*)smraw + 128 * LDAH };
    __half* Bs[2] = { (__half*)smraw + 2 * 128 * LDAH,
                      (__half*)smraw + 2 * 128 * LDAH + 32 * LDBH };

    const int tid = threadIdx.x;
    const int wid = tid >> 5;
    const int wm = wid & 3;
    const int wn = wid >> 2;
    const int m0 = blockIdx.y * 128;
    const int n0 = blockIdx.x * 128;

    wmma::fragment<wmma::accumulator, 16, 16, 16, float> acc[2][2];
    #pragma unroll
    for (int i = 0; i < 2; i++)
        #pragma unroll
        for (int j = 0; j < 2; j++) wmma::fill_fragment(acc[i][j], 0.0f);

    load_tiles(As[0], Bs[0], m0, n0, 0, tid);
    cp_commit();

    const int NT = KK / 32;
    for (int t = 0; t < NT; t++) {
        const int buf = t & 1;
        if (t + 1 < NT) {
            load_tiles(As[buf ^ 1], Bs[buf ^ 1], m0, n0, (t + 1) * 32, tid);
            cp_commit();
            cp_wait<1>();
        } else {
            cp_wait<0>();
        }
        __syncthreads();

        const __half* Asb = As[buf];
        const __half* Bsb = Bs[buf];
        #pragma unroll
        for (int kk = 0; kk < 32; kk += 16) {
            wmma::fragment<wmma::matrix_a, 16, 16, 16, __half, wmma::row_major> a[2];
            wmma::fragment<wmma::matrix_b, 16, 16, 16, __half, wmma::row_major> b[2];
            #pragma unroll
            for (int i = 0; i < 2; i++)
                wmma::load_matrix_sync(a[i], Asb + (wm * 32 + i * 16) * LDAH + kk, LDAH);
            #pragma unroll
            for (int j = 0; j < 2; j++)
                wmma::load_matrix_sync(b[j], Bsb + kk * LDBH + wn * 32 + j * 16, LDBH);
            #pragma unroll
            for (int i = 0; i < 2; i++)
                #pragma unroll
                for (int j = 0; j < 2; j++)
                    wmma::mma_sync(acc[i][j], a[i], b[j], acc[i][j]);
        }
        __syncthreads();
    }

    // ---- Stage C in smem (LDC=132, multiple of 4 floats = 16B) ----
    float* Cs = (float*)smraw;
    #pragma unroll
    for (int i = 0; i < 2; i++)
        #pragma unroll
        for (int j = 0; j < 2; j++)
            wmma::store_matrix_sync(Cs + (size_t)(wm * 32 + i * 16) * LDC + wn * 32 + j * 16,
                                    acc[i][j], LDC, wmma::mem_row_major);
    __syncthreads();

    // ---- Pass 1: add bias in place ----
    #pragma unroll
    for (int i = 0; i < 8; i++) {
        int idx = tid + i * 512;        // 4096 float4
        int row = idx >> 5;
        int c4 = (idx & 31) << 2;
        float4 c = *(const float4*)(Cs + row * LDC + c4);
        float4 bv = *(const float4*)(bias + n0 + c4);
        c.x += bv.x; c.y += bv.y; c.z += bv.z; c.w += bv.w;
        *(float4*)(Cs + row * LDC + c4) = c;
    }
    __syncthreads();

    // ---- Pass 2: fused RoPE / transpose epilogue ----
    const int which = n0 >> 11;             // 0=q, 1=k, 2=v
    const int h = (n0 & 2047) >> 7;
    const int b = m0 >> 11;
    const int s_base = m0 & 2047;

    if (which < 2) {
        __half* dstb = (which == 0 ? g_qh : g_kh) + ((size_t)(b * HH + h) * SS) * DD;
        const float scale = (which == 0) ? 0.08838834764831845f : 1.0f;
        #pragma unroll
        for (int i = 0; i < 8; i++) {
            int idx = tid + i * 512;
            int row = idx >> 5;
            int c4 = (idx & 31) << 2;       // d base, multiple of 4
            int s = s_base + row;
            float4 u = *(const float4*)(Cs + row * LDC + c4);
            float4 w = *(const float4*)(Cs + row * LDC + (c4 ^ 64));
            float sgn = (c4 < 64) ? -1.0f : 1.0f;
            const float2* scp = g_sc + (size_t)s * DD + c4;
            float2 sc0 = scp[0], sc1 = scp[1], sc2 = scp[2], sc3 = scp[3];
            float r0 = (u.x * sc0.y + sgn * w.x * sc0.x) * scale;
            float r1 = (u.y * sc1.y + sgn * w.y * sc1.x) * scale;
            float r2 = (u.z * sc2.y + sgn * w.z * sc2.x) * scale;
            float r3 = (u.w * sc3.y + sgn * w.w * sc3.x) * scale;
            __half2 h01 = __floats2half2_rn(r0, r1);
            __half2 h23 = __floats2half2_rn(r2, r3);
            __half* dp = dstb + (size_t)s * DD + c4;
            *(__half2*)(dp) = h01;
            *(__half2*)(dp + 2) = h23;
        }
    } else {
        // V: transpose to g_vt[b][h][d][s]
        __half* dstb = g_vt + ((size_t)(b * HH + h) * DD) * SS + s_base;
        #pragma unroll
        for (int i = 0; i < 8; i++) {
            int idx = tid + i * 512;
            int d = idx >> 5;
            int s4 = (idx & 31) << 2;
            float v0 = Cs[(s4 + 0) * LDC + d];
            float v1 = Cs[(s4 + 1) * LDC + d];
            float v2 = Cs[(s4 + 2) * LDC + d];
            float v3 = Cs[(s4 + 3) * LDC + d];
            __half2 h01 = __floats2half2_rn(v0, v1);
            __half2 h23 = __floats2half2_rn(v2, v3);
            __half* dp = dstb + (size_t)d * SS + s4;
            *(__half2*)(dp) = h01;
            *(__half2*)(dp + 2) = h23;
        }
    }
}

// ---------------------------------------------------------------------------
// Kernel 3: flash attention via fp16 mma.sync (m16n8k16, fp32 accum).
// 512 threads (16 warps). BM=BN=128, D=128. P overwrites K smem.
// ---------------------------------------------------------------------------
#define LDQH2 136
#define ATT_SMEM (3 * 128 * LDQH2 * 2 + 1024 * 4)

__global__ __launch_bounds__(512, 1) void attn_tc(float* __restrict__ out) {
    extern __shared__ char smraw[];
    __half* Qs = (__half*)smraw;             // [128][136]
    __half* KP = Qs + 128 * LDQH2;           // K tile, later P tile
    __half* Vt = KP + 128 * LDQH2;           // V^T tile: [d][s] 128x136
    float* mpart = (float*)(Vt + 128 * LDQH2);   // 4*128
    float* lpart = mpart + 512;                  // 4*128

    const int tid = threadIdx.x;
    const int wid = tid >> 5;
    const int lane = tid & 31;
    const int wm = wid & 3;
    const int wn = wid >> 2;
    const int g = lane >> 2;
    const int q = lane & 3;
    const int rbase = wm * 32;
    const int s0 = blockIdx.x * 128;
    const int h = blockIdx.y;
    const int b = blockIdx.z;

    const __half* qg = g_qh + ((size_t)(b * HH + h) * SS + s0) * DD;
    const __half* kg = g_kh + ((size_t)(b * HH + h) * SS) * DD;
    const __half* vtg = g_vt + ((size_t)(b * HH + h) * DD) * SS;

    #pragma unroll
    for (int i = 0; i < 4; i++) {
        int idx = tid + i * 512;
        int row = idx >> 4;
        int c8 = (idx & 15) << 3;
        cp_async16(Qs + row * LDQH2 + c8, qg + (size_t)row * DD + c8);
    }
    cp_commit();
    #pragma unroll
    for (int i = 0; i < 4; i++) {
        int idx = tid + i * 512;
        int row = idx >> 4;
        int c8 = (idx & 15) << 3;
        cp_async16(KP + row * LDQH2 + c8, kg + (size_t)row * DD + c8);
    }
    cp_commit();
    #pragma unroll
    for (int i = 0; i < 4; i++) {
        int idx = tid + i * 512;
        int row = idx >> 4;
        int c8 = (idx & 15) << 3;
        cp_async16(Vt + row * LDQH2 + c8, vtg + (size_t)row * SS + c8);
    }
    cp_commit();

    float o[2][4][4];
    #pragma unroll
    for (int mf = 0; mf < 2; mf++)
        #pragma unroll
        for (int nf = 0; nf < 4; nf++)
            #pragma unroll
            for (int e = 0; e < 4; e++) o[mf][nf][e] = 0.0f;
    float m_run[2][2] = {{-1e30f, -1e30f}, {-1e30f, -1e30f}};
    float l_run[2][2] = {{0.0f, 0.0f}, {0.0f, 0.0f}};

    for (int t = 0; t < SS / 128; t++) {
        cp_wait<1>();
        __syncthreads();

        // ---- S = Q K^T ----
        float s_[2][4][4];
        #pragma unroll
        for (int mf = 0; mf < 2; mf++)
            #pragma unroll
            for (int nf = 0; nf < 4; nf++)
                #pragma unroll
                for (int e = 0; e < 4; e++) s_[mf][nf][e] = 0.0f;

        #pragma unroll
        for (int kk = 0; kk < 8; kk++) {
            unsigned a[2][4];
            #pragma unroll
            for (int mf = 0; mf < 2; mf++) {
                const __half* qp = Qs + (rbase + mf * 16 + g) * LDQH2 + kk * 16 + q * 2;
                a[mf][0] = *(const unsigned*)(qp);
                a[mf][1] = *(const unsigned*)(qp + 8 * LDQH2);
                a[mf][2] = *(const unsigned*)(qp + 8);
                a[mf][3] = *(const unsigned*)(qp + 8 * LDQH2 + 8);
            }
            #pragma unroll
            for (int nf = 0; nf < 4; nf++) {
                const __half* kp = KP + (wn * 32 + nf * 8 + g) * LDQH2 + kk * 16 + q * 2;
                unsigned bf[2] = { *(const unsigned*)(kp), *(const unsigned*)(kp + 8) };
                mma_f16(s_[0][nf], a[0], bf);
                mma_f16(s_[1][nf], a[1], bf);
            }
        }

        // ---- local row max + quad reduce ----
        float lm[2][2] = {{-1e30f, -1e30f}, {-1e30f, -1e30f}};
        #pragma unroll
        for (int mf = 0; mf < 2; mf++)
            #pragma unroll
            for (int nf = 0; nf < 4; nf++) {
                lm[mf][0] = fmaxf(lm[mf][0], fmaxf(s_[mf][nf][0], s_[mf][nf][1]));
                lm[mf][1] = fmaxf(lm[mf][1], fmaxf(s_[mf][nf][2], s_[mf][nf][3]));
            }
        #pragma unroll
        for (int off = 1; off <= 2; off <<= 1)
            #pragma unroll
            for (int mf = 0; mf < 2; mf++)
                #pragma unroll
                for (int hf = 0; hf < 2; hf++)
                    lm[mf][hf] = fmaxf(lm[mf][hf],
                                       __shfl_xor_sync(0xffffffffu, lm[mf][hf], off));
        if (q == 0) {
            #pragma unroll
            for (int mf = 0; mf < 2; mf++)
                #pragma unroll
                for (int hf = 0; hf < 2; hf++)
                    mpart[wn * 128 + rbase + mf * 16 + g + hf * 8] = lm[mf][hf];
        }
        __syncthreads();

        // ---- joint max, alpha, exp, P store (half), local sums ----
        float mnew[2][2], al[2][2];
        #pragma unroll
        for (int mf = 0; mf < 2; mf++)
            #pragma unroll
            for (int hf = 0; hf < 2; hf++) {
                int r = rbase + mf * 16 + g + hf * 8;
                float mv = fmaxf(fmaxf(mpart[r], mpart[128 + r]),
                                 fmaxf(mpart[256 + r], mpart[384 + r]));
                float mn = fmaxf(m_run[mf][hf], mv);
                al[mf][hf] = __expf(m_run[mf][hf] - mn);
                m_run[mf][hf] = mn;
                mnew[mf][hf] = mn;
            }
        float ls[2][2] = {{0.0f, 0.0f}, {0.0f, 0.0f}};
        #pragma unroll
        for (int mf = 0; mf < 2; mf++)
            #pragma unroll
            for (int nf = 0; nf < 4; nf++) {
                float p0 = __expf(s_[mf][nf][0] - mnew[mf][0]);
                float p1 = __expf(s_[mf][nf][1] - mnew[mf][0]);
                float p2 = __expf(s_[mf][nf][2] - mnew[mf][1]);
                float p3 = __expf(s_[mf][nf][3] - mnew[mf][1]);
                ls[mf][0] += p0 + p1;
                ls[mf][1] += p2 + p3;
                int col = wn * 32 + nf * 8 + q * 2;
                *(__half2*)(KP + (rbase + mf * 16 + g) * LDQH2 + col) =
                    __floats2half2_rn(p0, p1);
                *(__half2*)(KP + (rbase + mf * 16 + g + 8) * LDQH2 + col) =
                    __floats2half2_rn(p2, p3);
            }
        #pragma unroll
        for (int off = 1; off <= 2; off <<= 1)
            #pragma unroll
            for (int mf = 0; mf < 2; mf++)
                #pragma unroll
                for (int hf = 0; hf < 2; hf++)
                    ls[mf][hf] += __shfl_xor_sync(0xffffffffu, ls[mf][hf], off);
        if (q == 0) {
            #pragma unroll
            for (int mf = 0; mf < 2; mf++)
                #pragma unroll
                for (int hf = 0; hf < 2; hf++)
                    lpart[wn * 128 + rbase + mf * 16 + g + hf * 8] = ls[mf][hf];
        }
        cp_wait<0>();
        __syncthreads();

        // ---- l update, O rescale ----
        #pragma unroll
        for (int mf = 0; mf < 2; mf++)
            #pragma unroll
            for (int hf = 0; hf < 2; hf++) {
                int r = rbase + mf * 16 + g + hf * 8;
                float lsum = lpart[r] + lpart[128 + r] + lpart[256 + r] + lpart[384 + r];
                l_run[mf][hf] = l_run[mf][hf] * al[mf][hf] + lsum;
            }
        #pragma unroll
        for (int mf = 0; mf < 2; mf++)
            #pragma unroll
            for (int nf = 0; nf < 4; nf++) {
                o[mf][nf][0] *= al[mf][0];
                o[mf][nf][1] *= al[mf][0];
                o[mf][nf][2] *= al[mf][1];
                o[mf][nf][3] *= al[mf][1];
            }

        // ---- O += P V ----
        #pragma unroll
        for (int kk = 0; kk < 8; kk++) {
            unsigned a[2][4];
            #pragma unroll
            for (int mf = 0; mf < 2; mf++) {
                const __half* pp = KP + (rbase + mf * 16 + g) * LDQH2 + kk * 16 + q * 2;
                a[mf][0] = *(const unsigned*)(pp);
                a[mf][1] = *(const unsigned*)(pp + 8 * LDQH2);
                a[mf][2] = *(const unsigned*)(pp + 8);
                a[mf][3] = *(const unsigned*)(pp + 8 * LDQH2 + 8);
            }
            #pragma unroll
            for (int nf = 0; nf < 4; nf++) {
                const __half* vp = Vt + (wn * 32 + nf * 8 + g) * LDQH2 + kk * 16 + q * 2;
                unsigned bf[2] = { *(const unsigned*)(vp), *(const unsigned*)(vp + 8) };
                mma_f16(o[0][nf], a[0], bf);
                mma_f16(o[1][nf], a[1], bf);
            }
        }
        __syncthreads();

        if (t + 1 < SS / 128) {
            const __half* kn = kg + (size_t)(t + 1) * 128 * DD;
            const __half* vn = vtg + (size_t)(t + 1) * 128;
            #pragma unroll
            for (int i = 0; i < 4; i++) {
                int idx = tid + i * 512;
                int row = idx >> 4;
                int c8 = (idx & 15) << 3;
                cp_async16(KP + row * LDQH2 + c8, kn + (size_t)row * DD + c8);
            }
            cp_commit();
            #pragma unroll
            for (int i = 0; i < 4; i++) {
                int idx = tid + i * 512;
                int row = idx >> 4;
                int c8 = (idx & 15) << 3;
                cp_async16(Vt + row * LDQH2 + c8, vn + (size_t)row * SS + c8);
            }
            cp_commit();
        }
    }

    // ---- epilogue ----
    float inv[2][2];
    #pragma unroll
    for (int mf = 0; mf < 2; mf++)
        #pragma unroll
        for (int hf = 0; hf < 2; hf++)
            inv[mf][hf] = 1.0f / l_run[mf][hf];

    #pragma unroll
    for (int mf = 0; mf < 2; mf++)
        #pragma unroll
        for (int nf = 0; nf < 4; nf++) {
            int col = wn * 32 + nf * 8 + q * 2;
            int row0 = s0 + rbase + mf * 16 + g;
            float2 w0 = { o[mf][nf][0] * inv[mf][0], o[mf][nf][1] * inv[mf][0] };
            float2 w1 = { o[mf][nf][2] * inv[mf][1], o[mf][nf][3] * inv[mf][1] };
            *(float2*)(out + ((size_t)(b * SS + row0) * HH + h) * DD + col) = w0;
            *(float2*)(out + ((size_t)(b * SS + row0 + 8) * HH + h) * DD + col) = w1;
        }
}

// ---------------------------------------------------------------------------
extern "C" void kernel_launch(void* const* d_in, const int* in_sizes, int n_in,
                              void* d_out, int out_size) {
    const float* x    = (const float*)d_in[0];
    const float* W    = (const float*)d_in[1];
    const float* bias = (const float*)d_in[2];
    float* out = (float*)d_out;

    cvt_x<<<(int)((size_t)MM * KK / 2048), 256>>>(x);
    cvt_w<<<(int)((size_t)KK * N3 / 2048), 256>>>(W);
    sc_table<<<SS * DD / 256, 256>>>();

    cudaFuncSetAttribute(qkv_gemm, cudaFuncAttributeMaxDynamicSharedMemorySize, GEMM_SMEM);
    dim3 g1(N3 / 128, MM / 128);
    qkv_gemm<<<g1, 512, GEMM_SMEM>>>(bias);

    cudaFuncSetAttribute(attn_tc, cudaFuncAttributeMaxDynamicSharedMemorySize, ATT_SMEM);
    dim3 g3(SS / 128, HH, BB);
    attn_tc<<<g3, 512, ATT_SMEM>>>(out);
}